// round 9
// baseline (speedup 1.0000x reference)
#include <cuda_runtime.h>
#include <cuda_bf16.h>
#include <math.h>
#include <cstdint>

// Problem constants (fixed shapes from the reference)
#define TOTAL_NODES 32768
#define BG   64
#define NN   512
#define VV   64
#define EE   1048576
#define INF_ 128
#define HH   256
#define OUTD 10
#define BUCKET 128   // fixed CSR bucket per node (avg deg 32, P(>128) ~ 0)

// ---------------- scratch (static device globals; no allocation) ----------------
__device__ float g_h  [TOTAL_NODES * HH];   // g (post-GCN)
__device__ float g_hw [TOTAL_NODES * HH];
__device__ float g_t1 [TOTAL_NODES * HH];
__device__ float g_t  [TOTAL_NODES * HH];
__device__ float g_proto[BG * HH];
__device__ float g_pn [BG];
__device__ float g_mw [BG * NN * VV];
__device__ float g_vn [BG * VV * HH];
__device__ float g_vn2[BG * VV * HH];
__device__ float g_vn3[BG * VV * HH];
__device__ float g_gf [BG * HH];
__device__ float g_m1 [BG * HH];
__device__ int   g_cursor[TOTAL_NODES];
__device__ float g_dinv  [TOTAL_NODES];
__device__ int   g_csr   [TOTAL_NODES * BUCKET];   // 16 MB fixed-stride buckets
// pre-split transposed weights: 6 slots of [N,K] bf16 (slot stride 256*256)
__device__ __nv_bfloat16 g_wh[6 * 256 * 256];
__device__ __nv_bfloat16 g_wl[6 * 256 * 256];

// ---------------- bucket CSR build (no scan) ----------------
__global__ void zero_cursor_kernel() {
    int i = blockIdx.x * blockDim.x + threadIdx.x;
    if (i < TOTAL_NODES) g_cursor[i] = 0;
}

__global__ void fill_kernel(const int* __restrict__ src, const int* __restrict__ dst) {
    int e = blockIdx.x * blockDim.x + threadIdx.x;
    if (e < EE) {
        int d = dst[e];
        int p = atomicAdd(&g_cursor[d], 1);
        g_csr[d * BUCKET + p] = src[e];
    }
}

__global__ void dinv_kernel() {
    int i = blockIdx.x * blockDim.x + threadIdx.x;
    if (i < TOTAL_NODES) g_dinv[i] = rsqrtf(1.0f + (float)g_cursor[i]);
}

// ---------------- fused weight split+transpose: all 6 weights in one launch ----------------
__global__ void split_all_kernel(const float* __restrict__ w0, const float* __restrict__ w1,
                                 const float* __restrict__ w2, const float* __restrict__ w3,
                                 const float* __restrict__ w4, const float* __restrict__ w5) {
    int slot = blockIdx.y;
    const float* W;
    switch (slot) {
        case 0: W = w0; break; case 1: W = w1; break; case 2: W = w2; break;
        case 3: W = w3; break; case 4: W = w4; break; default: W = w5; break;
    }
    int K = (slot == 0) ? INF_ : HH;
    int idx = blockIdx.x * 256 + threadIdx.x;
    if (idx >= K * HH) return;
    int k = idx / HH, n = idx % HH;
    float v = W[idx];
    __nv_bfloat16 hb = __float2bfloat16_rn(v);
    float r = v - __bfloat162float(hb);
    size_t o = (size_t)slot * (256 * 256) + (size_t)n * K + k;
    g_wh[o] = hb;
    g_wl[o] = __float2bfloat16_rn(r);
}

// ---------------- mma.sync bf16-split GEMM (R7 version) ----------------
#define MMA_BF16(d, a, b) \
    asm volatile("mma.sync.aligned.m16n8k16.row.col.f32.bf16.bf16.f32 " \
        "{%0,%1,%2,%3}, {%4,%5,%6,%7}, {%8,%9}, {%0,%1,%2,%3};" \
        : "+f"((d)[0]), "+f"((d)[1]), "+f"((d)[2]), "+f"((d)[3]) \
        : "r"((a)[0]), "r"((a)[1]), "r"((a)[2]), "r"((a)[3]), "r"((b)[0]), "r"((b)[1]))

#define APITCH 80   // bytes per 32-bf16 row (64B data + 16B pad -> conflict-free frag LDS)

template<bool RELU, bool BIAS>
__global__ void __launch_bounds__(256, 2) gemm_mma_kernel(
    const float* __restrict__ A,
    const __nv_bfloat16* __restrict__ Bh, const __nv_bfloat16* __restrict__ Bl,
    const float* __restrict__ bias, float* __restrict__ C,
    int M, int N, int K)
{
    __shared__ __align__(16) char sAh[128 * APITCH];
    __shared__ __align__(16) char sAl[128 * APITCH];
    __shared__ __align__(16) char sBh[128 * APITCH];
    __shared__ __align__(16) char sBl[128 * APITCH];

    const int tid = threadIdx.x;
    const int wid = tid >> 5, lane = tid & 31;
    const int warp_m = wid & 3;
    const int warp_n = wid >> 2;
    const int row0 = blockIdx.y * 128, col0 = blockIdx.x * 128;

    const int lr = lane >> 2;
    const int lk4 = (lane & 3) * 4;

    float acc[2][8][4];
#pragma unroll
    for (int i = 0; i < 2; i++)
#pragma unroll
        for (int j = 0; j < 8; j++)
#pragma unroll
            for (int q = 0; q < 4; q++) acc[i][j][q] = 0.f;

    for (int kc = 0; kc < K; kc += 32) {
        // ---- A tile: 128x32 fp32 -> hi/lo bf16, row-major pitch 80 ----
#pragma unroll
        for (int it = 0; it < 4; it++) {
            int i = tid + it * 256;
            int r = i >> 3, kq = i & 7;
            float4 v = *(const float4*)(A + (size_t)(row0 + r) * K + kc + kq * 4);
            __nv_bfloat16 h0 = __float2bfloat16_rn(v.x);
            __nv_bfloat16 h1 = __float2bfloat16_rn(v.y);
            __nv_bfloat16 h2 = __float2bfloat16_rn(v.z);
            __nv_bfloat16 h3 = __float2bfloat16_rn(v.w);
            __nv_bfloat16 l0 = __float2bfloat16_rn(v.x - __bfloat162float(h0));
            __nv_bfloat16 l1 = __float2bfloat16_rn(v.y - __bfloat162float(h1));
            __nv_bfloat16 l2 = __float2bfloat16_rn(v.z - __bfloat162float(h2));
            __nv_bfloat16 l3 = __float2bfloat16_rn(v.w - __bfloat162float(h3));
            uint2 uh, ul;
            uh.x = (uint32_t)__bfloat16_as_ushort(h0) | ((uint32_t)__bfloat16_as_ushort(h1) << 16);
            uh.y = (uint32_t)__bfloat16_as_ushort(h2) | ((uint32_t)__bfloat16_as_ushort(h3) << 16);
            ul.x = (uint32_t)__bfloat16_as_ushort(l0) | ((uint32_t)__bfloat16_as_ushort(l1) << 16);
            ul.y = (uint32_t)__bfloat16_as_ushort(l2) | ((uint32_t)__bfloat16_as_ushort(l3) << 16);
            *(uint2*)(sAh + r * APITCH + kq * 8) = uh;
            *(uint2*)(sAl + r * APITCH + kq * 8) = ul;
        }
        // ---- B tiles: 128 rows x 4 uint4 = 512 quads ----
#pragma unroll
        for (int it = 0; it < 2; it++) {
            int i = tid + it * 256;
            int n = i >> 2, kq = i & 3;
            size_t goff = (size_t)(col0 + n) * K + kc + kq * 8;
            *(uint4*)(sBh + n * APITCH + kq * 16) = *(const uint4*)(Bh + goff);
            *(uint4*)(sBl + n * APITCH + kq * 16) = *(const uint4*)(Bl + goff);
        }
        __syncthreads();

#pragma unroll
        for (int ks = 0; ks < 2; ks++) {
            const int kb = ks * 32;
            uint32_t ah[2][4], al[2][4];
#pragma unroll
            for (int mt = 0; mt < 2; mt++) {
                const char* base = sAh + (warp_m * 32 + mt * 16 + lr) * APITCH + kb + lk4;
                ah[mt][0] = *(const uint32_t*)base;
                ah[mt][1] = *(const uint32_t*)(base + 8 * APITCH);
                ah[mt][2] = *(const uint32_t*)(base + 16);
                ah[mt][3] = *(const uint32_t*)(base + 8 * APITCH + 16);
                const char* basel = sAl + (warp_m * 32 + mt * 16 + lr) * APITCH + kb + lk4;
                al[mt][0] = *(const uint32_t*)basel;
                al[mt][1] = *(const uint32_t*)(basel + 8 * APITCH);
                al[mt][2] = *(const uint32_t*)(basel + 16);
                al[mt][3] = *(const uint32_t*)(basel + 8 * APITCH + 16);
            }
#pragma unroll
            for (int nt = 0; nt < 8; nt++) {
                const char* bbase = sBh + (warp_n * 64 + nt * 8 + lr) * APITCH + kb + lk4;
                uint32_t bh[2], bl[2];
                bh[0] = *(const uint32_t*)bbase;
                bh[1] = *(const uint32_t*)(bbase + 16);
                const char* bbl = sBl + (warp_n * 64 + nt * 8 + lr) * APITCH + kb + lk4;
                bl[0] = *(const uint32_t*)bbl;
                bl[1] = *(const uint32_t*)(bbl + 16);
#pragma unroll
                for (int mt = 0; mt < 2; mt++) {
                    MMA_BF16(acc[mt][nt], ah[mt], bh);
                    MMA_BF16(acc[mt][nt], ah[mt], bl);
                    MMA_BF16(acc[mt][nt], al[mt], bh);
                }
            }
        }
        __syncthreads();
    }

    // ---- epilogue ----
#pragma unroll
    for (int mt = 0; mt < 2; mt++) {
        int r0 = row0 + warp_m * 32 + mt * 16 + lr;
#pragma unroll
        for (int nt = 0; nt < 8; nt++) {
            int c = col0 + warp_n * 64 + nt * 8 + (lane & 3) * 2;
            float v0 = acc[mt][nt][0], v1 = acc[mt][nt][1];
            float v2 = acc[mt][nt][2], v3 = acc[mt][nt][3];
            if (BIAS) {
                float b0 = bias[c], b1 = bias[c + 1];
                v0 += b0; v1 += b1; v2 += b0; v3 += b1;
            }
            if (RELU) {
                v0 = fmaxf(v0, 0.f); v1 = fmaxf(v1, 0.f);
                v2 = fmaxf(v2, 0.f); v3 = fmaxf(v3, 0.f);
            }
            *(float2*)(C + (size_t)r0 * N + c) = make_float2(v0, v1);
            *(float2*)(C + (size_t)(r0 + 8) * N + c) = make_float2(v2, v3);
        }
    }
}

// ---------------- generic fp32 GEMM (64x64 tile) for tiny shapes ----------------
template<bool RELU, bool BIAS>
__global__ void gemm_kernel(const float* __restrict__ A, const float* __restrict__ B,
                            const float* __restrict__ bias, float* __restrict__ C,
                            int M, int N, int K)
{
    __shared__ float As[16][68];
    __shared__ float Bs[16][68];
    const int tx = threadIdx.x, ty = threadIdx.y;
    const int tid = ty * 16 + tx;
    const int row0 = blockIdx.y * 64, col0 = blockIdx.x * 64;
    float acc[4][4] = {};
    for (int k0 = 0; k0 < K; k0 += 16) {
#pragma unroll
        for (int i = tid; i < 1024; i += 256) {
            int m = i >> 4, kk = i & 15;
            As[kk][m] = (row0 + m < M) ? A[(size_t)(row0 + m) * K + k0 + kk] : 0.0f;
        }
#pragma unroll
        for (int i = tid; i < 1024; i += 256) {
            int kk = i >> 6, n = i & 63;
            Bs[kk][n] = B[(size_t)(k0 + kk) * N + col0 + n];
        }
        __syncthreads();
#pragma unroll
        for (int kk = 0; kk < 16; kk++) {
            float4 a = *(const float4*)&As[kk][ty * 4];
            float4 b = *(const float4*)&Bs[kk][tx * 4];
            float av[4] = {a.x, a.y, a.z, a.w};
            float bv[4] = {b.x, b.y, b.z, b.w};
#pragma unroll
            for (int i = 0; i < 4; i++)
#pragma unroll
                for (int j = 0; j < 4; j++)
                    acc[i][j] += av[i] * bv[j];
        }
        __syncthreads();
    }
#pragma unroll
    for (int i = 0; i < 4; i++) {
        int r = row0 + ty * 4 + i;
        if (r >= M) continue;
#pragma unroll
        for (int j = 0; j < 4; j++) {
            int c = col0 + tx * 4 + j;
            float v = acc[i][j];
            if (BIAS) v += bias[c];
            if (RELU) v = fmaxf(v, 0.0f);
            C[(size_t)r * N + c] = v;
        }
    }
}

// ---------------- smem-staged GCN gather v2 ----------------
// grid (4 feature-chunks, 64 graphs), 512 threads (16 warps), 130KB smem.
// Warp-per-dst; csr read coalesced 32-wide per lane, coefs precomputed, shfl-broadcast.
#define GATHER_SMEM (NN * 64 * 4 + NN * 4)
__global__ void __launch_bounds__(512) gather_smem_kernel(const float* __restrict__ bgcn) {
    extern __shared__ float sm[];
    float* sH = sm;                        // [512][64]
    float* sdinv = sm + NN * 64;           // [512]
    const int b = blockIdx.y, chunk = blockIdx.x;
    const int tid = threadIdx.x, lane = tid & 31, wid = tid >> 5;   // 16 warps
    const float* hwb = g_hw + (size_t)b * NN * HH + chunk * 64;
    // stage feature chunk + dinv
    for (int i = tid; i < NN * 16; i += 512) {
        int r = i >> 4, q = i & 15;
        *(float4*)&sH[r * 64 + q * 4] = *(const float4*)(hwb + (size_t)r * HH + q * 4);
    }
    if (tid < NN) sdinv[tid] = g_dinv[b * NN + tid];
    __syncthreads();

    const float bias0 = bgcn[chunk * 64 + lane * 2];
    const float bias1 = bgcn[chunk * 64 + lane * 2 + 1];

    for (int d = wid; d < NN; d += 16) {
        int node = b * NN + d;
        const int* csr = g_csr + (size_t)node * BUCKET;
        int deg = g_cursor[node];
        float di = sdinv[d];
        float a0 = 0.f, a1 = 0.f;
        for (int e0 = 0; e0 < deg; e0 += 32) {
            int cnt = min(32, deg - e0);
            int sl = 0; float cl = 0.f;
            if (lane < cnt) {
                sl = csr[e0 + lane] & (NN - 1);   // coalesced 128B LDG serves 32 edges
                cl = sdinv[sl] * di;
            }
            if (cnt == 32) {
#pragma unroll 8
                for (int j = 0; j < 32; j++) {
                    int s = __shfl_sync(0xffffffffu, sl, j);
                    float c = __shfl_sync(0xffffffffu, cl, j);
                    float2 v = *(const float2*)&sH[s * 64 + lane * 2];
                    a0 += v.x * c; a1 += v.y * c;
                }
            } else {
                for (int j = 0; j < cnt; j++) {
                    int s = __shfl_sync(0xffffffffu, sl, j);
                    float c = __shfl_sync(0xffffffffu, cl, j);
                    float2 v = *(const float2*)&sH[s * 64 + lane * 2];
                    a0 += v.x * c; a1 += v.y * c;
                }
            }
        }
        float cs = di * di;   // self loop: 1/deg
        float2 vs = *(const float2*)&sH[d * 64 + lane * 2];
        a0 += vs.x * cs; a1 += vs.y * cs;
        a0 = fmaxf(a0 + bias0, 0.f);
        a1 = fmaxf(a1 + bias1, 0.f);
        *(float2*)&g_h[(size_t)node * HH + chunk * 64 + lane * 2] = make_float2(a0, a1);
    }
}

// ---------------- proto = mean_n t, pn = ||proto|| ----------------
__global__ void proto_kernel() {
    int b = blockIdx.x;
    int h = threadIdx.x;   // 256
    const float* tb = g_t + (size_t)b * NN * HH;
    float s = 0.f;
    for (int n = 0; n < NN; n++) s += tb[(size_t)n * HH + h];
    s *= (1.0f / NN);
    g_proto[b * HH + h] = s;
    __shared__ float red[256];
    red[h] = s * s;
    __syncthreads();
    for (int off = 128; off > 0; off >>= 1) {
        if (h < off) red[h] += red[h + off];
        __syncthreads();
    }
    if (h == 0) g_pn[b] = fmaxf(sqrtf(red[0]), 1e-8f);
}

// ---------------- fused attention + mw (warp per node) ----------------
__global__ void att_mw_kernel(const float* __restrict__ ew) {
    int w = (blockIdx.x * blockDim.x + threadIdx.x) >> 5;
    int lane = threadIdx.x & 31;
    if (w >= TOTAL_NODES) return;
    int b = w >> 9;
    const float* tr = g_t + (size_t)w * HH;
    const float* pr = g_proto + b * HH;
    float dot = 0.f, nrm = 0.f;
    for (int j = lane; j < HH; j += 32) {
        float v = tr[j];
        dot += v * pr[j];
        nrm += v * v;
    }
#pragma unroll
    for (int off = 16; off; off >>= 1) {
        dot += __shfl_xor_sync(0xffffffffu, dot, off);
        nrm += __shfl_xor_sync(0xffffffffu, nrm, off);
    }
    float tn = fmaxf(sqrtf(nrm), 1e-8f);
    float sim = dot / (tn * g_pn[b]);
    float a = 0.5f * (1.0f + sim);

    const float* e = ew + (size_t)w * VV;
    float v0 = e[lane] * a;
    float v1 = e[lane + 32] * a;
    float rs = v0 + v1;
#pragma unroll
    for (int off = 16; off; off >>= 1) rs += __shfl_xor_sync(0xffffffffu, rs, off);
    float sc = (rs == 0.0f) ? 1.0f : (1.0f / rs);
    float* m = g_mw + (size_t)w * VV;
    m[lane]      = v0 * sc;
    m[lane + 32] = v1 * sc;
}

// ---------------- vn[b] = mw[b]^T (V x N) @ g[b] (N x H) ----------------
__global__ void vn_gemm_kernel(const float* __restrict__ mw, const float* __restrict__ gfeat,
                               float* __restrict__ vn)
{
    __shared__ float As[16][68];
    __shared__ float Bs[16][68];
    int b = blockIdx.y;
    const float* mwb = mw    + (size_t)b * NN * VV;
    const float* gb  = gfeat + (size_t)b * NN * HH;
    float* vnb = vn + (size_t)b * VV * HH;
    int col0 = blockIdx.x * 64;
    int tx = threadIdx.x, ty = threadIdx.y, tid = ty * 16 + tx;
    float acc[4][4] = {};
    for (int k0 = 0; k0 < NN; k0 += 16) {
#pragma unroll
        for (int i = tid; i < 1024; i += 256) {
            int kk = i >> 6, m = i & 63;
            As[kk][m] = mwb[(size_t)(k0 + kk) * VV + m];
        }
#pragma unroll
        for (int i = tid; i < 1024; i += 256) {
            int kk = i >> 6, n = i & 63;
            Bs[kk][n] = gb[(size_t)(k0 + kk) * HH + col0 + n];
        }
        __syncthreads();
#pragma unroll
        for (int kk = 0; kk < 16; kk++) {
            float4 a = *(const float4*)&As[kk][ty * 4];
            float4 bq = *(const float4*)&Bs[kk][tx * 4];
            float av[4] = {a.x, a.y, a.z, a.w};
            float bv[4] = {bq.x, bq.y, bq.z, bq.w};
#pragma unroll
            for (int i = 0; i < 4; i++)
#pragma unroll
                for (int j = 0; j < 4; j++)
                    acc[i][j] += av[i] * bv[j];
        }
        __syncthreads();
    }
#pragma unroll
    for (int i = 0; i < 4; i++) {
        int v = ty * 4 + i;
#pragma unroll
        for (int j = 0; j < 4; j++) {
            int c = col0 + tx * 4 + j;
            vnb[(size_t)v * HH + c] = acc[i][j];
        }
    }
}

// ---------------- gf = mean over V ----------------
__global__ void gf_kernel() {
    int b = blockIdx.x, h = threadIdx.x;
    const float* v = g_vn3 + (size_t)b * VV * HH;
    float s = 0.f;
    for (int i = 0; i < VV; i++) s += v[i * HH + h];
    g_gf[b * HH + h] = s * (1.0f / VV);
}

// ---------------- out = m1 @ mW2 + mb2 ----------------
__global__ void out_kernel(const float* __restrict__ W, const float* __restrict__ bias,
                           float* __restrict__ out)
{
    int tid = threadIdx.x;
    if (tid >= BG * OUTD) return;
    int b = tid / OUTD, o = tid % OUTD;
    const float* m = g_m1 + b * HH;
    float s = bias[o];
    for (int k = 0; k < HH; k++) s += m[k] * W[k * OUTD + o];
    out[tid] = s;
}

// ---------------- launch ----------------
extern "C" void kernel_launch(void* const* d_in, const int* in_sizes, int n_in,
                              void* d_out, int out_size)
{
    const float* x     = (const float*)d_in[0];
    const int*   esrc  = (const int*)  d_in[1];
    const int*   edst  = (const int*)  d_in[2];
    const float* W_emb = (const float*)d_in[3];
    const float* b_emb = (const float*)d_in[4];
    const float* W_gcn = (const float*)d_in[5];
    const float* b_gcn = (const float*)d_in[6];
    const float* aW1   = (const float*)d_in[7];
    const float* ab1   = (const float*)d_in[8];
    const float* aW2   = (const float*)d_in[9];
    const float* ab2   = (const float*)d_in[10];
    const float* vW1   = (const float*)d_in[11];
    const float* vb1   = (const float*)d_in[12];
    const float* vW2   = (const float*)d_in[13];
    const float* vb2   = (const float*)d_in[14];
    const float* mW1   = (const float*)d_in[15];
    const float* mb1   = (const float*)d_in[16];
    const float* mW2   = (const float*)d_in[17];
    const float* mb2   = (const float*)d_in[18];
    const float* ew    = (const float*)d_in[19];
    float* out = (float*)d_out;

    float *h, *hw, *t1, *t, *mw, *vn, *vn2, *vn3, *gf, *m1;
    __nv_bfloat16 *wh, *wl;
    cudaGetSymbolAddress((void**)&h,   g_h);
    cudaGetSymbolAddress((void**)&hw,  g_hw);
    cudaGetSymbolAddress((void**)&t1,  g_t1);
    cudaGetSymbolAddress((void**)&t,   g_t);
    cudaGetSymbolAddress((void**)&mw,  g_mw);
    cudaGetSymbolAddress((void**)&vn,  g_vn);
    cudaGetSymbolAddress((void**)&vn2, g_vn2);
    cudaGetSymbolAddress((void**)&vn3, g_vn3);
    cudaGetSymbolAddress((void**)&gf,  g_gf);
    cudaGetSymbolAddress((void**)&m1,  g_m1);
    cudaGetSymbolAddress((void**)&wh,  g_wh);
    cudaGetSymbolAddress((void**)&wl,  g_wl);

    static bool attr_done = false;
    if (!attr_done) {
        cudaFuncSetAttribute(gather_smem_kernel, cudaFuncAttributeMaxDynamicSharedMemorySize, GATHER_SMEM);
        attr_done = true;
    }

    dim3 t2d(16, 16);
    const int WS = 256 * 256;   // weight slot stride

    // split+transpose all weights into bf16 hi/lo: ONE launch
    split_all_kernel<<<dim3(256, 6), 256>>>(W_emb, W_gcn, aW1, aW2, vW1, vW2);

    // bucket CSR build
    zero_cursor_kernel<<<TOTAL_NODES / 256, 256>>>();
    fill_kernel<<<EE / 256, 256>>>(esrc, edst);
    dinv_kernel<<<TOTAL_NODES / 256, 256>>>();

    // h = x @ W_emb + b_emb
    gemm_mma_kernel<false, true><<<dim3(HH / 128, TOTAL_NODES / 128), 256>>>(
        x, wh + 0 * WS, wl + 0 * WS, b_emb, h, TOTAL_NODES, HH, INF_);
    // hw = h @ W_gcn
    gemm_mma_kernel<false, false><<<dim3(HH / 128, TOTAL_NODES / 128), 256>>>(
        h, wh + 1 * WS, wl + 1 * WS, nullptr, hw, TOTAL_NODES, HH, HH);
    // g = relu(agg + b_gcn)  (overwrites g_h)
    gather_smem_kernel<<<dim3(4, BG), 512, GATHER_SMEM>>>(b_gcn);

    // t = relu(g@aW1+ab1)@aW2+ab2
    gemm_mma_kernel<true, true><<<dim3(HH / 128, TOTAL_NODES / 128), 256>>>(
        h, wh + 2 * WS, wl + 2 * WS, ab1, t1, TOTAL_NODES, HH, HH);
    gemm_mma_kernel<false, true><<<dim3(HH / 128, TOTAL_NODES / 128), 256>>>(
        t1, wh + 3 * WS, wl + 3 * WS, ab2, t, TOTAL_NODES, HH, HH);

    // attention
    proto_kernel<<<BG, 256>>>();
    att_mw_kernel<<<TOTAL_NODES * 32 / 256, 256>>>(ew);

    // vn = mw^T @ g (per graph), then vn MLP
    vn_gemm_kernel<<<dim3(HH / 64, BG), t2d>>>(mw, h, vn);
    gemm_mma_kernel<true, true><<<dim3(HH / 128, BG * VV / 128), 256>>>(
        vn, wh + 4 * WS, wl + 4 * WS, vb1, vn2, BG * VV, HH, HH);
    gemm_mma_kernel<false, true><<<dim3(HH / 128, BG * VV / 128), 256>>>(
        vn2, wh + 5 * WS, wl + 5 * WS, vb2, vn3, BG * VV, HH, HH);

    // readout
    gf_kernel<<<BG, 256>>>();
    gemm_kernel<true, true><<<dim3(HH / 64, 1), t2d>>>(gf, mW1, mb1, m1, BG, HH, HH);
    out_kernel<<<1, 640>>>(mW2, mb2, out);
}

// round 10
// speedup vs baseline: 1.1593x; 1.1593x over previous
#include <cuda_runtime.h>
#include <cuda_bf16.h>
#include <math.h>
#include <cstdint>

// Problem constants (fixed shapes from the reference)
#define TOTAL_NODES 32768
#define BG   64
#define NN   512
#define VV   64
#define EE   1048576
#define INF_ 128
#define HH   256
#define OUTD 10
#define BUCKET 128   // fixed CSR bucket per node (avg deg 32, P(>128) ~ 0)

// ---------------- scratch (static device globals; no allocation) ----------------
__device__ float g_h  [TOTAL_NODES * HH];   // g (post-GCN)
__device__ float g_hw [TOTAL_NODES * HH];
__device__ float g_t1 [TOTAL_NODES * HH];
__device__ float g_t  [TOTAL_NODES * HH];
__device__ float g_proto[BG * HH];
__device__ float g_pn [BG];
__device__ float g_mw [BG * NN * VV];
__device__ float g_vn [BG * VV * HH];
__device__ float g_vn2[BG * VV * HH];
__device__ float g_vn3[BG * VV * HH];
__device__ float g_gf [BG * HH];
__device__ float g_m1 [BG * HH];
__device__ int   g_cursor[TOTAL_NODES];
__device__ float g_dinv  [TOTAL_NODES];
__device__ int   g_csr   [TOTAL_NODES * BUCKET];   // 16 MB fixed-stride buckets
// pre-split transposed weights: 6 slots of [N,K] bf16 (slot stride 256*256)
__device__ __nv_bfloat16 g_wh[6 * 256 * 256];
__device__ __nv_bfloat16 g_wl[6 * 256 * 256];

// ---------------- bucket CSR build (no scan) ----------------
__global__ void zero_cursor_kernel() {
    int i = blockIdx.x * blockDim.x + threadIdx.x;
    if (i < TOTAL_NODES) g_cursor[i] = 0;
}

__global__ void fill_kernel(const int* __restrict__ src, const int* __restrict__ dst) {
    int e = blockIdx.x * blockDim.x + threadIdx.x;
    if (e < EE) {
        int d = dst[e];
        int p = atomicAdd(&g_cursor[d], 1);
        g_csr[d * BUCKET + p] = src[e];
    }
}

__global__ void dinv_kernel() {
    int i = blockIdx.x * blockDim.x + threadIdx.x;
    if (i < TOTAL_NODES) g_dinv[i] = rsqrtf(1.0f + (float)g_cursor[i]);
}

// ---------------- fused weight split+transpose: all 6 weights in one launch ----------------
__global__ void split_all_kernel(const float* __restrict__ w0, const float* __restrict__ w1,
                                 const float* __restrict__ w2, const float* __restrict__ w3,
                                 const float* __restrict__ w4, const float* __restrict__ w5) {
    int slot = blockIdx.y;
    const float* W;
    switch (slot) {
        case 0: W = w0; break; case 1: W = w1; break; case 2: W = w2; break;
        case 3: W = w3; break; case 4: W = w4; break; default: W = w5; break;
    }
    int K = (slot == 0) ? INF_ : HH;
    int idx = blockIdx.x * 256 + threadIdx.x;
    if (idx >= K * HH) return;
    int k = idx / HH, n = idx % HH;
    float v = W[idx];
    __nv_bfloat16 hb = __float2bfloat16_rn(v);
    float r = v - __bfloat162float(hb);
    size_t o = (size_t)slot * (256 * 256) + (size_t)n * K + k;
    g_wh[o] = hb;
    g_wl[o] = __float2bfloat16_rn(r);
}

// ---------------- mma.sync bf16-split GEMM, double-buffered + cp.async ----------------
// D = Ah*Bh + Ah*Bl + Al*Bh (fp32 accum). 128x128 CTA tile, BK=32, 8 warps (4x2).
#define MMA_BF16(d, a, b) \
    asm volatile("mma.sync.aligned.m16n8k16.row.col.f32.bf16.bf16.f32 " \
        "{%0,%1,%2,%3}, {%4,%5,%6,%7}, {%8,%9}, {%0,%1,%2,%3};" \
        : "+f"((d)[0]), "+f"((d)[1]), "+f"((d)[2]), "+f"((d)[3]) \
        : "r"((a)[0]), "r"((a)[1]), "r"((a)[2]), "r"((a)[3]), "r"((b)[0]), "r"((b)[1]))

#define APITCH 80                    // bytes per 32-bf16 row (64B data + 16B pad)
#define TILE_BYTES (128 * APITCH)    // 10240
#define BUF_BYTES  (4 * TILE_BYTES)  // Ah,Al,Bh,Bl per buffer
#define GEMM_SMEM  (2 * BUF_BYTES)   // 81920

__device__ __forceinline__ uint32_t smem_u32(const void* p) {
    uint32_t a;
    asm("{ .reg .u64 t; cvta.to.shared.u64 t, %1; cvt.u32.u64 %0, t; }" : "=r"(a) : "l"(p));
    return a;
}
#define CP_ASYNC16(saddr, gptr) \
    asm volatile("cp.async.cg.shared.global [%0], [%1], 16;" :: "r"(saddr), "l"(gptr))
#define CP_COMMIT() asm volatile("cp.async.commit_group;" ::: "memory")
#define CP_WAIT0()  asm volatile("cp.async.wait_group 0;" ::: "memory")

template<bool RELU, bool BIAS>
__global__ void __launch_bounds__(256, 2) gemm_mma_kernel(
    const float* __restrict__ A,
    const __nv_bfloat16* __restrict__ Bh, const __nv_bfloat16* __restrict__ Bl,
    const float* __restrict__ bias, float* __restrict__ C,
    int M, int N, int K)
{
    extern __shared__ char smem[];
    const uint32_t sb32 = smem_u32(smem);

    const int tid = threadIdx.x;
    const int wid = tid >> 5, lane = tid & 31;
    const int warp_m = wid & 3;
    const int warp_n = wid >> 2;
    const int row0 = blockIdx.y * 128, col0 = blockIdx.x * 128;

    const int lr = lane >> 2;
    const int lk4 = (lane & 3) * 4;

    // loader indices
    const int a_r  = tid >> 3, a_kq = tid & 7;         // wrong decomposition? no:
    // A loader uses i = tid + it*256 (it 0..3), r = i>>3, kq = i&7
    // B loader uses i = tid + it*256 (it 0..1), n = i>>2, kq = i&3
    (void)a_r; (void)a_kq;

    float acc[2][8][4];
#pragma unroll
    for (int i = 0; i < 2; i++)
#pragma unroll
        for (int j = 0; j < 8; j++)
#pragma unroll
            for (int q = 0; q < 4; q++) acc[i][j][q] = 0.f;

    const int nk = K >> 5;
    float4 pa[4];

    // ---- helper lambdas ----
    auto ldg_A = [&](int kc) {
#pragma unroll
        for (int it = 0; it < 4; it++) {
            int i = tid + it * 256;
            int r = i >> 3, kq = i & 7;
            pa[it] = *(const float4*)(A + (size_t)(row0 + r) * K + kc + kq * 4);
        }
    };
    auto sts_A = [&](int bb) {
        char* dAh = smem + bb * BUF_BYTES;
        char* dAl = dAh + TILE_BYTES;
#pragma unroll
        for (int it = 0; it < 4; it++) {
            int i = tid + it * 256;
            int r = i >> 3, kq = i & 7;
            float4 v = pa[it];
            __nv_bfloat16 h0 = __float2bfloat16_rn(v.x);
            __nv_bfloat16 h1 = __float2bfloat16_rn(v.y);
            __nv_bfloat16 h2 = __float2bfloat16_rn(v.z);
            __nv_bfloat16 h3 = __float2bfloat16_rn(v.w);
            __nv_bfloat16 l0 = __float2bfloat16_rn(v.x - __bfloat162float(h0));
            __nv_bfloat16 l1 = __float2bfloat16_rn(v.y - __bfloat162float(h1));
            __nv_bfloat16 l2 = __float2bfloat16_rn(v.z - __bfloat162float(h2));
            __nv_bfloat16 l3 = __float2bfloat16_rn(v.w - __bfloat162float(h3));
            uint2 uh, ul;
            uh.x = (uint32_t)__bfloat16_as_ushort(h0) | ((uint32_t)__bfloat16_as_ushort(h1) << 16);
            uh.y = (uint32_t)__bfloat16_as_ushort(h2) | ((uint32_t)__bfloat16_as_ushort(h3) << 16);
            ul.x = (uint32_t)__bfloat16_as_ushort(l0) | ((uint32_t)__bfloat16_as_ushort(l1) << 16);
            ul.y = (uint32_t)__bfloat16_as_ushort(l2) | ((uint32_t)__bfloat16_as_ushort(l3) << 16);
            *(uint2*)(dAh + r * APITCH + kq * 8) = uh;
            *(uint2*)(dAl + r * APITCH + kq * 8) = ul;
        }
    };
    auto cpasync_B = [&](int kc, int bb) {
        uint32_t dBh = sb32 + bb * BUF_BYTES + 2 * TILE_BYTES;
        uint32_t dBl = dBh + TILE_BYTES;
#pragma unroll
        for (int it = 0; it < 2; it++) {
            int i = tid + it * 256;
            int n = i >> 2, kq = i & 3;
            size_t goff = (size_t)(col0 + n) * K + kc + kq * 8;
            CP_ASYNC16(dBh + n * APITCH + kq * 16, Bh + goff);
            CP_ASYNC16(dBl + n * APITCH + kq * 16, Bl + goff);
        }
        CP_COMMIT();
    };

    // ---- prologue: stage chunk 0 into buffer 0 ----
    ldg_A(0);
    cpasync_B(0, 0);
    sts_A(0);
    CP_WAIT0();
    __syncthreads();

    int buf = 0;
    for (int c = 0; c < nk; c++) {
        // prefetch chunk c+1
        if (c + 1 < nk) {
            ldg_A((c + 1) << 5);
            cpasync_B((c + 1) << 5, buf ^ 1);
        }

        // compute on current buffer
        const char* sAh = smem + buf * BUF_BYTES;
        const char* sAl = sAh + TILE_BYTES;
        const char* sBh = sAh + 2 * TILE_BYTES;
        const char* sBl = sAh + 3 * TILE_BYTES;
#pragma unroll
        for (int ks = 0; ks < 2; ks++) {
            const int kb = ks * 32;
            uint32_t ah[2][4], al[2][4];
#pragma unroll
            for (int mt = 0; mt < 2; mt++) {
                const char* base = sAh + (warp_m * 32 + mt * 16 + lr) * APITCH + kb + lk4;
                ah[mt][0] = *(const uint32_t*)base;
                ah[mt][1] = *(const uint32_t*)(base + 8 * APITCH);
                ah[mt][2] = *(const uint32_t*)(base + 16);
                ah[mt][3] = *(const uint32_t*)(base + 8 * APITCH + 16);
                const char* basel = sAl + (warp_m * 32 + mt * 16 + lr) * APITCH + kb + lk4;
                al[mt][0] = *(const uint32_t*)basel;
                al[mt][1] = *(const uint32_t*)(basel + 8 * APITCH);
                al[mt][2] = *(const uint32_t*)(basel + 16);
                al[mt][3] = *(const uint32_t*)(basel + 8 * APITCH + 16);
            }
#pragma unroll
            for (int nt = 0; nt < 8; nt++) {
                const char* bbase = sBh + (warp_n * 64 + nt * 8 + lr) * APITCH + kb + lk4;
                uint32_t bh[2], bl[2];
                bh[0] = *(const uint32_t*)bbase;
                bh[1] = *(const uint32_t*)(bbase + 16);
                const char* bbl = sBl + (warp_n * 64 + nt * 8 + lr) * APITCH + kb + lk4;
                bl[0] = *(const uint32_t*)bbl;
                bl[1] = *(const uint32_t*)(bbl + 16);
#pragma unroll
                for (int mt = 0; mt < 2; mt++) {
                    MMA_BF16(acc[mt][nt], ah[mt], bh);
                    MMA_BF16(acc[mt][nt], ah[mt], bl);
                    MMA_BF16(acc[mt][nt], al[mt], bh);
                }
            }
        }

        // stage chunk c+1 A into next buffer; drain B cp.async
        if (c + 1 < nk) {
            sts_A(buf ^ 1);
            CP_WAIT0();
        }
        __syncthreads();
        buf ^= 1;
    }

    // ---- epilogue ----
#pragma unroll
    for (int mt = 0; mt < 2; mt++) {
        int r0 = row0 + warp_m * 32 + mt * 16 + lr;
#pragma unroll
        for (int nt = 0; nt < 8; nt++) {
            int c = col0 + warp_n * 64 + nt * 8 + (lane & 3) * 2;
            float v0 = acc[mt][nt][0], v1 = acc[mt][nt][1];
            float v2 = acc[mt][nt][2], v3 = acc[mt][nt][3];
            if (BIAS) {
                float b0 = bias[c], b1 = bias[c + 1];
                v0 += b0; v1 += b1; v2 += b0; v3 += b1;
            }
            if (RELU) {
                v0 = fmaxf(v0, 0.f); v1 = fmaxf(v1, 0.f);
                v2 = fmaxf(v2, 0.f); v3 = fmaxf(v3, 0.f);
            }
            *(float2*)(C + (size_t)r0 * N + c) = make_float2(v0, v1);
            *(float2*)(C + (size_t)(r0 + 8) * N + c) = make_float2(v2, v3);
        }
    }
}

// ---------------- generic fp32 GEMM (64x64 tile) for tiny shapes ----------------
template<bool RELU, bool BIAS>
__global__ void gemm_kernel(const float* __restrict__ A, const float* __restrict__ B,
                            const float* __restrict__ bias, float* __restrict__ C,
                            int M, int N, int K)
{
    __shared__ float As[16][68];
    __shared__ float Bs[16][68];
    const int tx = threadIdx.x, ty = threadIdx.y;
    const int tid = ty * 16 + tx;
    const int row0 = blockIdx.y * 64, col0 = blockIdx.x * 64;
    float acc[4][4] = {};
    for (int k0 = 0; k0 < K; k0 += 16) {
#pragma unroll
        for (int i = tid; i < 1024; i += 256) {
            int m = i >> 4, kk = i & 15;
            As[kk][m] = (row0 + m < M) ? A[(size_t)(row0 + m) * K + k0 + kk] : 0.0f;
        }
#pragma unroll
        for (int i = tid; i < 1024; i += 256) {
            int kk = i >> 6, n = i & 63;
            Bs[kk][n] = B[(size_t)(k0 + kk) * N + col0 + n];
        }
        __syncthreads();
#pragma unroll
        for (int kk = 0; kk < 16; kk++) {
            float4 a = *(const float4*)&As[kk][ty * 4];
            float4 b = *(const float4*)&Bs[kk][tx * 4];
            float av[4] = {a.x, a.y, a.z, a.w};
            float bv[4] = {b.x, b.y, b.z, b.w};
#pragma unroll
            for (int i = 0; i < 4; i++)
#pragma unroll
                for (int j = 0; j < 4; j++)
                    acc[i][j] += av[i] * bv[j];
        }
        __syncthreads();
    }
#pragma unroll
    for (int i = 0; i < 4; i++) {
        int r = row0 + ty * 4 + i;
        if (r >= M) continue;
#pragma unroll
        for (int j = 0; j < 4; j++) {
            int c = col0 + tx * 4 + j;
            float v = acc[i][j];
            if (BIAS) v += bias[c];
            if (RELU) v = fmaxf(v, 0.0f);
            C[(size_t)r * N + c] = v;
        }
    }
}

// ---------------- GCN gather (bucket CSR, MLP=4 unrolled) + bias + relu ----------------
__global__ void gather_gcn_kernel(const float* __restrict__ bgcn) {
    int node = blockIdx.x * 4 + threadIdx.y;
    int t = threadIdx.x;              // 0..63
    const float4* hw4 = (const float4*)g_hw;
    const int* csr = g_csr + node * BUCKET;
    int deg = g_cursor[node];
    float di = g_dinv[node];
    float4 acc = make_float4(0.f, 0.f, 0.f, 0.f);
    int e = 0;
    for (; e + 4 <= deg; e += 4) {
        int s0 = csr[e], s1 = csr[e + 1], s2 = csr[e + 2], s3 = csr[e + 3];
        float c0 = g_dinv[s0] * di, c1 = g_dinv[s1] * di;
        float c2 = g_dinv[s2] * di, c3 = g_dinv[s3] * di;
        float4 v0 = hw4[(size_t)s0 * 64 + t];
        float4 v1 = hw4[(size_t)s1 * 64 + t];
        float4 v2 = hw4[(size_t)s2 * 64 + t];
        float4 v3 = hw4[(size_t)s3 * 64 + t];
        acc.x += v0.x * c0 + v1.x * c1 + v2.x * c2 + v3.x * c3;
        acc.y += v0.y * c0 + v1.y * c1 + v2.y * c2 + v3.y * c3;
        acc.z += v0.z * c0 + v1.z * c1 + v2.z * c2 + v3.z * c3;
        acc.w += v0.w * c0 + v1.w * c1 + v2.w * c2 + v3.w * c3;
    }
    for (; e < deg; e++) {
        int s = csr[e];
        float coef = g_dinv[s] * di;
        float4 v = hw4[(size_t)s * 64 + t];
        acc.x += v.x * coef; acc.y += v.y * coef;
        acc.z += v.z * coef; acc.w += v.w * coef;
    }
    float cs = di * di;
    float4 v = hw4[(size_t)node * 64 + t];
    acc.x += v.x * cs; acc.y += v.y * cs; acc.z += v.z * cs; acc.w += v.w * cs;
    float4 bb = ((const float4*)bgcn)[t];
    acc.x = fmaxf(acc.x + bb.x, 0.f);
    acc.y = fmaxf(acc.y + bb.y, 0.f);
    acc.z = fmaxf(acc.z + bb.z, 0.f);
    acc.w = fmaxf(acc.w + bb.w, 0.f);
    ((float4*)g_h)[(size_t)node * 64 + t] = acc;
}

// ---------------- proto = mean_n t, pn = ||proto|| ----------------
__global__ void proto_kernel() {
    int b = blockIdx.x;
    int h = threadIdx.x;   // 256
    const float* tb = g_t + (size_t)b * NN * HH;
    float s = 0.f;
    for (int n = 0; n < NN; n++) s += tb[(size_t)n * HH + h];
    s *= (1.0f / NN);
    g_proto[b * HH + h] = s;
    __shared__ float red[256];
    red[h] = s * s;
    __syncthreads();
    for (int off = 128; off > 0; off >>= 1) {
        if (h < off) red[h] += red[h + off];
        __syncthreads();
    }
    if (h == 0) g_pn[b] = fmaxf(sqrtf(red[0]), 1e-8f);
}

// ---------------- fused attention + mw (warp per node) ----------------
__global__ void att_mw_kernel(const float* __restrict__ ew) {
    int w = (blockIdx.x * blockDim.x + threadIdx.x) >> 5;
    int lane = threadIdx.x & 31;
    if (w >= TOTAL_NODES) return;
    int b = w >> 9;
    const float* tr = g_t + (size_t)w * HH;
    const float* pr = g_proto + b * HH;
    float dot = 0.f, nrm = 0.f;
    for (int j = lane; j < HH; j += 32) {
        float v = tr[j];
        dot += v * pr[j];
        nrm += v * v;
    }
#pragma unroll
    for (int off = 16; off; off >>= 1) {
        dot += __shfl_xor_sync(0xffffffffu, dot, off);
        nrm += __shfl_xor_sync(0xffffffffu, nrm, off);
    }
    float tn = fmaxf(sqrtf(nrm), 1e-8f);
    float sim = dot / (tn * g_pn[b]);
    float a = 0.5f * (1.0f + sim);

    const float* e = ew + (size_t)w * VV;
    float v0 = e[lane] * a;
    float v1 = e[lane + 32] * a;
    float rs = v0 + v1;
#pragma unroll
    for (int off = 16; off; off >>= 1) rs += __shfl_xor_sync(0xffffffffu, rs, off);
    float sc = (rs == 0.0f) ? 1.0f : (1.0f / rs);
    float* m = g_mw + (size_t)w * VV;
    m[lane]      = v0 * sc;
    m[lane + 32] = v1 * sc;
}

// ---------------- vn[b] = mw[b]^T (V x N) @ g[b] (N x H) ----------------
__global__ void vn_gemm_kernel(const float* __restrict__ mw, const float* __restrict__ gfeat,
                               float* __restrict__ vn)
{
    __shared__ float As[16][68];
    __shared__ float Bs[16][68];
    int b = blockIdx.y;
    const float* mwb = mw    + (size_t)b * NN * VV;
    const float* gb  = gfeat + (size_t)b * NN * HH;
    float* vnb = vn + (size_t)b * VV * HH;
    int col0 = blockIdx.x * 64;
    int tx = threadIdx.x, ty = threadIdx.y, tid = ty * 16 + tx;
    float acc[4][4] = {};
    for (int k0 = 0; k0 < NN; k0 += 16) {
#pragma unroll
        for (int i = tid; i < 1024; i += 256) {
            int kk = i >> 6, m = i & 63;
            As[kk][m] = mwb[(size_t)(k0 + kk) * VV + m];
        }
#pragma unroll
        for (int i = tid; i < 1024; i += 256) {
            int kk = i >> 6, n = i & 63;
            Bs[kk][n] = gb[(size_t)(k0 + kk) * HH + col0 + n];
        }
        __syncthreads();
#pragma unroll
        for (int kk = 0; kk < 16; kk++) {
            float4 a = *(const float4*)&As[kk][ty * 4];
            float4 bq = *(const float4*)&Bs[kk][tx * 4];
            float av[4] = {a.x, a.y, a.z, a.w};
            float bv[4] = {bq.x, bq.y, bq.z, bq.w};
#pragma unroll
            for (int i = 0; i < 4; i++)
#pragma unroll
                for (int j = 0; j < 4; j++)
                    acc[i][j] += av[i] * bv[j];
        }
        __syncthreads();
    }
#pragma unroll
    for (int i = 0; i < 4; i++) {
        int v = ty * 4 + i;
#pragma unroll
        for (int j = 0; j < 4; j++) {
            int c = col0 + tx * 4 + j;
            vnb[(size_t)v * HH + c] = acc[i][j];
        }
    }
}

// ---------------- gf = mean over V ----------------
__global__ void gf_kernel() {
    int b = blockIdx.x, h = threadIdx.x;
    const float* v = g_vn3 + (size_t)b * VV * HH;
    float s = 0.f;
    for (int i = 0; i < VV; i++) s += v[i * HH + h];
    g_gf[b * HH + h] = s * (1.0f / VV);
}

// ---------------- out = m1 @ mW2 + mb2 ----------------
__global__ void out_kernel(const float* __restrict__ W, const float* __restrict__ bias,
                           float* __restrict__ out)
{
    int tid = threadIdx.x;
    if (tid >= BG * OUTD) return;
    int b = tid / OUTD, o = tid % OUTD;
    const float* m = g_m1 + b * HH;
    float s = bias[o];
    for (int k = 0; k < HH; k++) s += m[k] * W[k * OUTD + o];
    out[tid] = s;
}

// ---------------- launch ----------------
extern "C" void kernel_launch(void* const* d_in, const int* in_sizes, int n_in,
                              void* d_out, int out_size)
{
    const float* x     = (const float*)d_in[0];
    const int*   esrc  = (const int*)  d_in[1];
    const int*   edst  = (const int*)  d_in[2];
    const float* W_emb = (const float*)d_in[3];
    const float* b_emb = (const float*)d_in[4];
    const float* W_gcn = (const float*)d_in[5];
    const float* b_gcn = (const float*)d_in[6];
    const float* aW1   = (const float*)d_in[7];
    const float* ab1   = (const float*)d_in[8];
    const float* aW2   = (const float*)d_in[9];
    const float* ab2   = (const float*)d_in[10];
    const float* vW1   = (const float*)d_in[11];
    const float* vb1   = (const float*)d_in[12];
    const float* vW2   = (const float*)d_in[13];
    const float* vb2   = (const float*)d_in[14];
    const float* mW1   = (const float*)d_in[15];
    const float* mb1   = (const float*)d_in[16];
    const float* mW2   = (const float*)d_in[17];
    const float* mb2   = (const float*)d_in[18];
    const float* ew    = (const float*)d_in[19];
    float* out = (float*)d_out;

    float *h, *hw, *t1, *t, *mw, *vn, *vn2, *vn3, *gf, *m1;
    __nv_bfloat16 *wh, *wl;
    cudaGetSymbolAddress((void**)&h,   g_h);
    cudaGetSymbolAddress((void**)&hw,  g_hw);
    cudaGetSymbolAddress((void**)&t1,  g_t1);
    cudaGetSymbolAddress((void**)&t,   g_t);
    cudaGetSymbolAddress((void**)&mw,  g_mw);
    cudaGetSymbolAddress((void**)&vn,  g_vn);
    cudaGetSymbolAddress((void**)&vn2, g_vn2);
    cudaGetSymbolAddress((void**)&vn3, g_vn3);
    cudaGetSymbolAddress((void**)&gf,  g_gf);
    cudaGetSymbolAddress((void**)&m1,  g_m1);
    cudaGetSymbolAddress((void**)&wh,  g_wh);
    cudaGetSymbolAddress((void**)&wl,  g_wl);

    static bool attr_done = false;
    if (!attr_done) {
        cudaFuncSetAttribute(gemm_mma_kernel<false, true>,  cudaFuncAttributeMaxDynamicSharedMemorySize, GEMM_SMEM);
        cudaFuncSetAttribute(gemm_mma_kernel<false, false>, cudaFuncAttributeMaxDynamicSharedMemorySize, GEMM_SMEM);
        cudaFuncSetAttribute(gemm_mma_kernel<true,  true>,  cudaFuncAttributeMaxDynamicSharedMemorySize, GEMM_SMEM);
        attr_done = true;
    }

    dim3 t2d(16, 16);
    const int WS = 256 * 256;   // weight slot stride

    // split+transpose all weights into bf16 hi/lo: ONE launch
    split_all_kernel<<<dim3(256, 6), 256>>>(W_emb, W_gcn, aW1, aW2, vW1, vW2);

    // bucket CSR build
    zero_cursor_kernel<<<TOTAL_NODES / 256, 256>>>();
    fill_kernel<<<EE / 256, 256>>>(esrc, edst);
    dinv_kernel<<<TOTAL_NODES / 256, 256>>>();

    // h = x @ W_emb + b_emb
    gemm_mma_kernel<false, true><<<dim3(HH / 128, TOTAL_NODES / 128), 256, GEMM_SMEM>>>(
        x, wh + 0 * WS, wl + 0 * WS, b_emb, h, TOTAL_NODES, HH, INF_);
    // hw = h @ W_gcn
    gemm_mma_kernel<false, false><<<dim3(HH / 128, TOTAL_NODES / 128), 256, GEMM_SMEM>>>(
        h, wh + 1 * WS, wl + 1 * WS, nullptr, hw, TOTAL_NODES, HH, HH);
    // g = relu(agg + b_gcn)  (overwrites g_h)
    gather_gcn_kernel<<<TOTAL_NODES / 4, dim3(64, 4)>>>(b_gcn);

    // t = relu(g@aW1+ab1)@aW2+ab2
    gemm_mma_kernel<true, true><<<dim3(HH / 128, TOTAL_NODES / 128), 256, GEMM_SMEM>>>(
        h, wh + 2 * WS, wl + 2 * WS, ab1, t1, TOTAL_NODES, HH, HH);
    gemm_mma_kernel<false, true><<<dim3(HH / 128, TOTAL_NODES / 128), 256, GEMM_SMEM>>>(
        t1, wh + 3 * WS, wl + 3 * WS, ab2, t, TOTAL_NODES, HH, HH);

    // attention
    proto_kernel<<<BG, 256>>>();
    att_mw_kernel<<<TOTAL_NODES * 32 / 256, 256>>>(ew);

    // vn = mw^T @ g (per graph), then vn MLP
    vn_gemm_kernel<<<dim3(HH / 64, BG), t2d>>>(mw, h, vn);
    gemm_mma_kernel<true, true><<<dim3(HH / 128, BG * VV / 128), 256, GEMM_SMEM>>>(
        vn, wh + 4 * WS, wl + 4 * WS, vb1, vn2, BG * VV, HH, HH);
    gemm_mma_kernel<false, true><<<dim3(HH / 128, BG * VV / 128), 256, GEMM_SMEM>>>(
        vn2, wh + 5 * WS, wl + 5 * WS, vb2, vn3, BG * VV, HH, HH);

    // readout
    gf_kernel<<<BG, 256>>>();
    gemm_kernel<true, true><<<dim3(HH / 64, 1), t2d>>>(gf, mW1, mb1, m1, BG, HH, HH);
    out_kernel<<<1, 640>>>(mW2, mb2, out);
}

// round 11
// speedup vs baseline: 1.3020x; 1.1231x over previous
#include <cuda_runtime.h>
#include <cuda_bf16.h>
#include <math.h>
#include <cstdint>

// Problem constants (fixed shapes from the reference)
#define TOTAL_NODES 32768
#define BG   64
#define NN   512
#define VV   64
#define EE   1048576
#define INF_ 128
#define HH   256
#define OUTD 10
#define BUCKET 128   // fixed CSR bucket per node (avg deg 32, P(>128) ~ 0)

// ---------------- scratch (static device globals; no allocation) ----------------
__device__ float g_h  [TOTAL_NODES * HH];   // g (post-GCN)
__device__ float g_hw [TOTAL_NODES * HH];
__device__ float g_t1 [TOTAL_NODES * HH];
__device__ float g_t  [TOTAL_NODES * HH];
__device__ float g_proto[BG * HH];
__device__ float g_pn [BG];
__device__ float g_mw [BG * NN * VV];
__device__ float g_vn [BG * VV * HH];
__device__ float g_vn2[BG * VV * HH];
__device__ float g_vn3[BG * VV * HH];
__device__ float g_gf [BG * HH];
__device__ float g_m1 [BG * HH];
__device__ int   g_cursor[TOTAL_NODES];
__device__ float g_dinv  [TOTAL_NODES];
__device__ int   g_csr   [TOTAL_NODES * BUCKET];   // 16 MB fixed-stride buckets
// pre-split transposed weights: 6 slots of [N,K] bf16 (slot stride 256*256)
__device__ __nv_bfloat16 g_wh[6 * 256 * 256];
__device__ __nv_bfloat16 g_wl[6 * 256 * 256];

// ---------------- bucket CSR build (no scan) ----------------
__global__ void zero_cursor_kernel() {
    int i = blockIdx.x * blockDim.x + threadIdx.x;
    if (i < TOTAL_NODES) g_cursor[i] = 0;
}

__global__ void fill_kernel(const int* __restrict__ src, const int* __restrict__ dst) {
    int e = blockIdx.x * blockDim.x + threadIdx.x;
    if (e < EE) {
        int d = dst[e];
        int p = atomicAdd(&g_cursor[d], 1);
        g_csr[d * BUCKET + p] = src[e];
    }
}

__global__ void dinv_kernel() {
    int i = blockIdx.x * blockDim.x + threadIdx.x;
    if (i < TOTAL_NODES) g_dinv[i] = rsqrtf(1.0f + (float)g_cursor[i]);
}

// ---------------- fused weight split+transpose: all 6 weights in one launch ----------------
__global__ void split_all_kernel(const float* __restrict__ w0, const float* __restrict__ w1,
                                 const float* __restrict__ w2, const float* __restrict__ w3,
                                 const float* __restrict__ w4, const float* __restrict__ w5) {
    int slot = blockIdx.y;
    const float* W;
    switch (slot) {
        case 0: W = w0; break; case 1: W = w1; break; case 2: W = w2; break;
        case 3: W = w3; break; case 4: W = w4; break; default: W = w5; break;
    }
    int K = (slot == 0) ? INF_ : HH;
    int idx = blockIdx.x * 256 + threadIdx.x;
    if (idx >= K * HH) return;
    int k = idx / HH, n = idx % HH;
    float v = W[idx];
    __nv_bfloat16 hb = __float2bfloat16_rn(v);
    float r = v - __bfloat162float(hb);
    size_t o = (size_t)slot * (256 * 256) + (size_t)n * K + k;
    g_wh[o] = hb;
    g_wl[o] = __float2bfloat16_rn(r);
}

// ---------------- mma.sync bf16-split GEMM, double-buffered + cp.async ----------------
#define MMA_BF16(d, a, b) \
    asm volatile("mma.sync.aligned.m16n8k16.row.col.f32.bf16.bf16.f32 " \
        "{%0,%1,%2,%3}, {%4,%5,%6,%7}, {%8,%9}, {%0,%1,%2,%3};" \
        : "+f"((d)[0]), "+f"((d)[1]), "+f"((d)[2]), "+f"((d)[3]) \
        : "r"((a)[0]), "r"((a)[1]), "r"((a)[2]), "r"((a)[3]), "r"((b)[0]), "r"((b)[1]))

#define APITCH 80                    // bytes per 32-bf16 row (64B data + 16B pad)
#define TILE_BYTES (128 * APITCH)    // 10240
#define BUF_BYTES  (4 * TILE_BYTES)  // Ah,Al,Bh,Bl per buffer
#define GEMM_SMEM  (2 * BUF_BYTES)   // 81920

__device__ __forceinline__ uint32_t smem_u32(const void* p) {
    uint32_t a;
    asm("{ .reg .u64 t; cvta.to.shared.u64 t, %1; cvt.u32.u64 %0, t; }" : "=r"(a) : "l"(p));
    return a;
}
#define CP_ASYNC16(saddr, gptr) \
    asm volatile("cp.async.cg.shared.global [%0], [%1], 16;" :: "r"(saddr), "l"(gptr))
#define CP_COMMIT() asm volatile("cp.async.commit_group;" ::: "memory")
#define CP_WAIT0()  asm volatile("cp.async.wait_group 0;" ::: "memory")

__device__ __forceinline__ uint32_t pack_split_hi(float a, float b,
                                                  __nv_bfloat16& ha, __nv_bfloat16& hb) {
    ha = __float2bfloat16_rn(a);
    hb = __float2bfloat16_rn(b);
    return (uint32_t)__bfloat16_as_ushort(ha) | ((uint32_t)__bfloat16_as_ushort(hb) << 16);
}
__device__ __forceinline__ uint32_t pack_lo(float a, float b, __nv_bfloat16 ha, __nv_bfloat16 hb) {
    __nv_bfloat16 la = __float2bfloat16_rn(a - __bfloat162float(ha));
    __nv_bfloat16 lb = __float2bfloat16_rn(b - __bfloat162float(hb));
    return (uint32_t)__bfloat16_as_ushort(la) | ((uint32_t)__bfloat16_as_ushort(lb) << 16);
}

template<bool RELU, bool BIAS>
__global__ void __launch_bounds__(256, 2) gemm_mma_kernel(
    const float* __restrict__ A,
    const __nv_bfloat16* __restrict__ Bh, const __nv_bfloat16* __restrict__ Bl,
    const float* __restrict__ bias, float* __restrict__ C,
    int M, int N, int K)
{
    extern __shared__ char smem[];
    const uint32_t sb32 = smem_u32(smem);

    const int tid = threadIdx.x;
    const int wid = tid >> 5, lane = tid & 31;
    const int warp_m = wid & 3;
    const int warp_n = wid >> 2;
    const int row0 = blockIdx.y * 128, col0 = blockIdx.x * 128;

    const int lr = lane >> 2;
    const int lk4 = (lane & 3) * 4;

    float acc[2][8][4];
#pragma unroll
    for (int i = 0; i < 2; i++)
#pragma unroll
        for (int j = 0; j < 8; j++)
#pragma unroll
            for (int q = 0; q < 4; q++) acc[i][j][q] = 0.f;

    const int nk = K >> 5;
    float4 pa[4];

    auto ldg_A = [&](int kc) {
#pragma unroll
        for (int it = 0; it < 4; it++) {
            int i = tid + it * 256;
            int r = i >> 3, kq = i & 7;
            pa[it] = *(const float4*)(A + (size_t)(row0 + r) * K + kc + kq * 4);
        }
    };
    auto sts_A = [&](int bb) {
        char* dAh = smem + bb * BUF_BYTES;
        char* dAl = dAh + TILE_BYTES;
#pragma unroll
        for (int it = 0; it < 4; it++) {
            int i = tid + it * 256;
            int r = i >> 3, kq = i & 7;
            float4 v = pa[it];
            __nv_bfloat16 h0, h1, h2, h3;
            uint2 uh, ul;
            uh.x = pack_split_hi(v.x, v.y, h0, h1);
            uh.y = pack_split_hi(v.z, v.w, h2, h3);
            ul.x = pack_lo(v.x, v.y, h0, h1);
            ul.y = pack_lo(v.z, v.w, h2, h3);
            *(uint2*)(dAh + r * APITCH + kq * 8) = uh;
            *(uint2*)(dAl + r * APITCH + kq * 8) = ul;
        }
    };
    auto cpasync_B = [&](int kc, int bb) {
        uint32_t dBh = sb32 + bb * BUF_BYTES + 2 * TILE_BYTES;
        uint32_t dBl = dBh + TILE_BYTES;
#pragma unroll
        for (int it = 0; it < 2; it++) {
            int i = tid + it * 256;
            int n = i >> 2, kq = i & 3;
            size_t goff = (size_t)(col0 + n) * K + kc + kq * 8;
            CP_ASYNC16(dBh + n * APITCH + kq * 16, Bh + goff);
            CP_ASYNC16(dBl + n * APITCH + kq * 16, Bl + goff);
        }
        CP_COMMIT();
    };

    ldg_A(0);
    cpasync_B(0, 0);
    sts_A(0);
    CP_WAIT0();
    __syncthreads();

    int buf = 0;
    for (int c = 0; c < nk; c++) {
        if (c + 1 < nk) {
            ldg_A((c + 1) << 5);
            cpasync_B((c + 1) << 5, buf ^ 1);
        }

        const char* sAh = smem + buf * BUF_BYTES;
        const char* sAl = sAh + TILE_BYTES;
        const char* sBh = sAh + 2 * TILE_BYTES;
        const char* sBl = sAh + 3 * TILE_BYTES;
#pragma unroll
        for (int ks = 0; ks < 2; ks++) {
            const int kb = ks * 32;
            uint32_t ah[2][4], al[2][4];
#pragma unroll
            for (int mt = 0; mt < 2; mt++) {
                const char* base = sAh + (warp_m * 32 + mt * 16 + lr) * APITCH + kb + lk4;
                ah[mt][0] = *(const uint32_t*)base;
                ah[mt][1] = *(const uint32_t*)(base + 8 * APITCH);
                ah[mt][2] = *(const uint32_t*)(base + 16);
                ah[mt][3] = *(const uint32_t*)(base + 8 * APITCH + 16);
                const char* basel = sAl + (warp_m * 32 + mt * 16 + lr) * APITCH + kb + lk4;
                al[mt][0] = *(const uint32_t*)basel;
                al[mt][1] = *(const uint32_t*)(basel + 8 * APITCH);
                al[mt][2] = *(const uint32_t*)(basel + 16);
                al[mt][3] = *(const uint32_t*)(basel + 8 * APITCH + 16);
            }
#pragma unroll
            for (int nt = 0; nt < 8; nt++) {
                const char* bbase = sBh + (warp_n * 64 + nt * 8 + lr) * APITCH + kb + lk4;
                uint32_t bh[2], bl[2];
                bh[0] = *(const uint32_t*)bbase;
                bh[1] = *(const uint32_t*)(bbase + 16);
                const char* bbl = sBl + (warp_n * 64 + nt * 8 + lr) * APITCH + kb + lk4;
                bl[0] = *(const uint32_t*)bbl;
                bl[1] = *(const uint32_t*)(bbl + 16);
#pragma unroll
                for (int mt = 0; mt < 2; mt++) {
                    MMA_BF16(acc[mt][nt], ah[mt], bh);
                    MMA_BF16(acc[mt][nt], ah[mt], bl);
                    MMA_BF16(acc[mt][nt], al[mt], bh);
                }
            }
        }

        if (c + 1 < nk) {
            sts_A(buf ^ 1);
            CP_WAIT0();
        }
        __syncthreads();
        buf ^= 1;
    }

#pragma unroll
    for (int mt = 0; mt < 2; mt++) {
        int r0 = row0 + warp_m * 32 + mt * 16 + lr;
#pragma unroll
        for (int nt = 0; nt < 8; nt++) {
            int c = col0 + warp_n * 64 + nt * 8 + (lane & 3) * 2;
            float v0 = acc[mt][nt][0], v1 = acc[mt][nt][1];
            float v2 = acc[mt][nt][2], v3 = acc[mt][nt][3];
            if (BIAS) {
                float b0 = bias[c], b1 = bias[c + 1];
                v0 += b0; v1 += b1; v2 += b0; v3 += b1;
            }
            if (RELU) {
                v0 = fmaxf(v0, 0.f); v1 = fmaxf(v1, 0.f);
                v2 = fmaxf(v2, 0.f); v3 = fmaxf(v3, 0.f);
            }
            *(float2*)(C + (size_t)r0 * N + c) = make_float2(v0, v1);
            *(float2*)(C + (size_t)(r0 + 8) * N + c) = make_float2(v2, v3);
        }
    }
}

// ---------------- vn mma GEMM: vn[b] = mw[b]^T (64x512) @ g[b] (512x256) ----------------
// A = mw^T (column-major source), B = g (row-major [K,N] source). Both staged via
// pair-transpose: thread packs (k,k+1) bf16 pair into one uint32 -> fragment layout.
// Tile M=64, N=128, BK=32. 8 warps: warp_m = wid&1 (32 rows), warp_n = wid>>1 (32 cols).
__global__ void __launch_bounds__(256) vn_mma_kernel(
    const float* __restrict__ mw, const float* __restrict__ gfeat, float* __restrict__ vn)
{
    __shared__ __align__(16) char sAh[64 * APITCH];
    __shared__ __align__(16) char sAl[64 * APITCH];
    __shared__ __align__(16) char sBh[128 * APITCH];
    __shared__ __align__(16) char sBl[128 * APITCH];

    const int b = blockIdx.y;
    const int col0 = blockIdx.x * 128;
    const float* mwb = mw + (size_t)b * NN * VV;      // [node][64]
    const float* gb  = gfeat + (size_t)b * NN * HH;   // [node][256]
    float* vnb = vn + (size_t)b * VV * HH;

    const int tid = threadIdx.x;
    const int wid = tid >> 5, lane = tid & 31;
    const int warp_m = wid & 1;      // 2 x 32 rows
    const int warp_n = wid >> 1;     // 4 x 32 cols
    const int lr = lane >> 2;
    const int lk4 = (lane & 3) * 4;

    float acc[2][4][4];
#pragma unroll
    for (int i = 0; i < 2; i++)
#pragma unroll
        for (int j = 0; j < 4; j++)
#pragma unroll
            for (int q = 0; q < 4; q++) acc[i][j][q] = 0.f;

    for (int kc = 0; kc < NN; kc += 32) {
        // stage A: 64 v x 16 k-pairs = 1024 pairs
#pragma unroll
        for (int it = 0; it < 4; it++) {
            int i = tid + it * 256;
            int v = i & 63, kp = i >> 6;
            float x0 = mwb[(size_t)(kc + 2 * kp) * VV + v];
            float x1 = mwb[(size_t)(kc + 2 * kp + 1) * VV + v];
            __nv_bfloat16 h0, h1;
            uint32_t uh = pack_split_hi(x0, x1, h0, h1);
            uint32_t ul = pack_lo(x0, x1, h0, h1);
            *(uint32_t*)(sAh + v * APITCH + kp * 4) = uh;
            *(uint32_t*)(sAl + v * APITCH + kp * 4) = ul;
        }
        // stage B: 128 n x 16 k-pairs = 2048 pairs
#pragma unroll
        for (int it = 0; it < 8; it++) {
            int i = tid + it * 256;
            int n = i & 127, kp = i >> 7;
            float x0 = gb[(size_t)(kc + 2 * kp) * HH + col0 + n];
            float x1 = gb[(size_t)(kc + 2 * kp + 1) * HH + col0 + n];
            __nv_bfloat16 h0, h1;
            uint32_t uh = pack_split_hi(x0, x1, h0, h1);
            uint32_t ul = pack_lo(x0, x1, h0, h1);
            *(uint32_t*)(sBh + n * APITCH + kp * 4) = uh;
            *(uint32_t*)(sBl + n * APITCH + kp * 4) = ul;
        }
        __syncthreads();

#pragma unroll
        for (int ks = 0; ks < 2; ks++) {
            const int kb = ks * 32;
            uint32_t ah[2][4], al[2][4];
#pragma unroll
            for (int mt = 0; mt < 2; mt++) {
                const char* base = sAh + (warp_m * 32 + mt * 16 + lr) * APITCH + kb + lk4;
                ah[mt][0] = *(const uint32_t*)base;
                ah[mt][1] = *(const uint32_t*)(base + 8 * APITCH);
                ah[mt][2] = *(const uint32_t*)(base + 16);
                ah[mt][3] = *(const uint32_t*)(base + 8 * APITCH + 16);
                const char* basel = sAl + (warp_m * 32 + mt * 16 + lr) * APITCH + kb + lk4;
                al[mt][0] = *(const uint32_t*)basel;
                al[mt][1] = *(const uint32_t*)(basel + 8 * APITCH);
                al[mt][2] = *(const uint32_t*)(basel + 16);
                al[mt][3] = *(const uint32_t*)(basel + 8 * APITCH + 16);
            }
#pragma unroll
            for (int nt = 0; nt < 4; nt++) {
                const char* bbase = sBh + (warp_n * 32 + nt * 8 + lr) * APITCH + kb + lk4;
                uint32_t bh[2], bl[2];
                bh[0] = *(const uint32_t*)bbase;
                bh[1] = *(const uint32_t*)(bbase + 16);
                const char* bbl = sBl + (warp_n * 32 + nt * 8 + lr) * APITCH + kb + lk4;
                bl[0] = *(const uint32_t*)bbl;
                bl[1] = *(const uint32_t*)(bbl + 16);
#pragma unroll
                for (int mt = 0; mt < 2; mt++) {
                    MMA_BF16(acc[mt][nt], ah[mt], bh);
                    MMA_BF16(acc[mt][nt], ah[mt], bl);
                    MMA_BF16(acc[mt][nt], al[mt], bh);
                }
            }
        }
        __syncthreads();
    }

#pragma unroll
    for (int mt = 0; mt < 2; mt++) {
        int r0 = warp_m * 32 + mt * 16 + lr;
#pragma unroll
        for (int nt = 0; nt < 4; nt++) {
            int c = col0 + warp_n * 32 + nt * 8 + (lane & 3) * 2;
            *(float2*)(vnb + (size_t)r0 * HH + c) = make_float2(acc[mt][nt][0], acc[mt][nt][1]);
            *(float2*)(vnb + (size_t)(r0 + 8) * HH + c) = make_float2(acc[mt][nt][2], acc[mt][nt][3]);
        }
    }
}

// ---------------- generic fp32 GEMM (64x64 tile) for tiny shapes ----------------
template<bool RELU, bool BIAS>
__global__ void gemm_kernel(const float* __restrict__ A, const float* __restrict__ B,
                            const float* __restrict__ bias, float* __restrict__ C,
                            int M, int N, int K)
{
    __shared__ float As[16][68];
    __shared__ float Bs[16][68];
    const int tx = threadIdx.x, ty = threadIdx.y;
    const int tid = ty * 16 + tx;
    const int row0 = blockIdx.y * 64, col0 = blockIdx.x * 64;
    float acc[4][4] = {};
    for (int k0 = 0; k0 < K; k0 += 16) {
#pragma unroll
        for (int i = tid; i < 1024; i += 256) {
            int m = i >> 4, kk = i & 15;
            As[kk][m] = (row0 + m < M) ? A[(size_t)(row0 + m) * K + k0 + kk] : 0.0f;
        }
#pragma unroll
        for (int i = tid; i < 1024; i += 256) {
            int kk = i >> 6, n = i & 63;
            Bs[kk][n] = B[(size_t)(k0 + kk) * N + col0 + n];
        }
        __syncthreads();
#pragma unroll
        for (int kk = 0; kk < 16; kk++) {
            float4 a = *(const float4*)&As[kk][ty * 4];
            float4 b = *(const float4*)&Bs[kk][tx * 4];
            float av[4] = {a.x, a.y, a.z, a.w};
            float bv[4] = {b.x, b.y, b.z, b.w};
#pragma unroll
            for (int i = 0; i < 4; i++)
#pragma unroll
                for (int j = 0; j < 4; j++)
                    acc[i][j] += av[i] * bv[j];
        }
        __syncthreads();
    }
#pragma unroll
    for (int i = 0; i < 4; i++) {
        int r = row0 + ty * 4 + i;
        if (r >= M) continue;
#pragma unroll
        for (int j = 0; j < 4; j++) {
            int c = col0 + tx * 4 + j;
            float v = acc[i][j];
            if (BIAS) v += bias[c];
            if (RELU) v = fmaxf(v, 0.0f);
            C[(size_t)r * N + c] = v;
        }
    }
}

// ---------------- GCN gather (bucket CSR, MLP=4 unrolled) + bias + relu ----------------
__global__ void gather_gcn_kernel(const float* __restrict__ bgcn) {
    int node = blockIdx.x * 4 + threadIdx.y;
    int t = threadIdx.x;              // 0..63
    const float4* hw4 = (const float4*)g_hw;
    const int* csr = g_csr + node * BUCKET;
    int deg = g_cursor[node];
    float di = g_dinv[node];
    float4 acc = make_float4(0.f, 0.f, 0.f, 0.f);
    int e = 0;
    for (; e + 4 <= deg; e += 4) {
        int s0 = csr[e], s1 = csr[e + 1], s2 = csr[e + 2], s3 = csr[e + 3];
        float c0 = g_dinv[s0] * di, c1 = g_dinv[s1] * di;
        float c2 = g_dinv[s2] * di, c3 = g_dinv[s3] * di;
        float4 v0 = hw4[(size_t)s0 * 64 + t];
        float4 v1 = hw4[(size_t)s1 * 64 + t];
        float4 v2 = hw4[(size_t)s2 * 64 + t];
        float4 v3 = hw4[(size_t)s3 * 64 + t];
        acc.x += v0.x * c0 + v1.x * c1 + v2.x * c2 + v3.x * c3;
        acc.y += v0.y * c0 + v1.y * c1 + v2.y * c2 + v3.y * c3;
        acc.z += v0.z * c0 + v1.z * c1 + v2.z * c2 + v3.z * c3;
        acc.w += v0.w * c0 + v1.w * c1 + v2.w * c2 + v3.w * c3;
    }
    for (; e < deg; e++) {
        int s = csr[e];
        float coef = g_dinv[s] * di;
        float4 v = hw4[(size_t)s * 64 + t];
        acc.x += v.x * coef; acc.y += v.y * coef;
        acc.z += v.z * coef; acc.w += v.w * coef;
    }
    float cs = di * di;
    float4 v = hw4[(size_t)node * 64 + t];
    acc.x += v.x * cs; acc.y += v.y * cs; acc.z += v.z * cs; acc.w += v.w * cs;
    float4 bb = ((const float4*)bgcn)[t];
    acc.x = fmaxf(acc.x + bb.x, 0.f);
    acc.y = fmaxf(acc.y + bb.y, 0.f);
    acc.z = fmaxf(acc.z + bb.z, 0.f);
    acc.w = fmaxf(acc.w + bb.w, 0.f);
    ((float4*)g_h)[(size_t)node * 64 + t] = acc;
}

// ---------------- proto = mean_n t, pn = ||proto|| ----------------
__global__ void proto_kernel() {
    int b = blockIdx.x;
    int h = threadIdx.x;   // 256
    const float* tb = g_t + (size_t)b * NN * HH;
    float s = 0.f;
    for (int n = 0; n < NN; n++) s += tb[(size_t)n * HH + h];
    s *= (1.0f / NN);
    g_proto[b * HH + h] = s;
    __shared__ float red[256];
    red[h] = s * s;
    __syncthreads();
    for (int off = 128; off > 0; off >>= 1) {
        if (h < off) red[h] += red[h + off];
        __syncthreads();
    }
    if (h == 0) g_pn[b] = fmaxf(sqrtf(red[0]), 1e-8f);
}

// ---------------- fused attention + mw (warp per node) ----------------
__global__ void att_mw_kernel(const float* __restrict__ ew) {
    int w = (blockIdx.x * blockDim.x + threadIdx.x) >> 5;
    int lane = threadIdx.x & 31;
    if (w >= TOTAL_NODES) return;
    int b = w >> 9;
    const float* tr = g_t + (size_t)w * HH;
    const float* pr = g_proto + b * HH;
    float dot = 0.f, nrm = 0.f;
    for (int j = lane; j < HH; j += 32) {
        float v = tr[j];
        dot += v * pr[j];
        nrm += v * v;
    }
#pragma unroll
    for (int off = 16; off; off >>= 1) {
        dot += __shfl_xor_sync(0xffffffffu, dot, off);
        nrm += __shfl_xor_sync(0xffffffffu, nrm, off);
    }
    float tn = fmaxf(sqrtf(nrm), 1e-8f);
    float sim = dot / (tn * g_pn[b]);
    float a = 0.5f * (1.0f + sim);

    const float* e = ew + (size_t)w * VV;
    float v0 = e[lane] * a;
    float v1 = e[lane + 32] * a;
    float rs = v0 + v1;
#pragma unroll
    for (int off = 16; off; off >>= 1) rs += __shfl_xor_sync(0xffffffffu, rs, off);
    float sc = (rs == 0.0f) ? 1.0f : (1.0f / rs);
    float* m = g_mw + (size_t)w * VV;
    m[lane]      = v0 * sc;
    m[lane + 32] = v1 * sc;
}

// ---------------- gf = mean over V ----------------
__global__ void gf_kernel() {
    int b = blockIdx.x, h = threadIdx.x;
    const float* v = g_vn3 + (size_t)b * VV * HH;
    float s = 0.f;
    for (int i = 0; i < VV; i++) s += v[i * HH + h];
    g_gf[b * HH + h] = s * (1.0f / VV);
}

// ---------------- out = m1 @ mW2 + mb2 ----------------
__global__ void out_kernel(const float* __restrict__ W, const float* __restrict__ bias,
                           float* __restrict__ out)
{
    int tid = threadIdx.x;
    if (tid >= BG * OUTD) return;
    int b = tid / OUTD, o = tid % OUTD;
    const float* m = g_m1 + b * HH;
    float s = bias[o];
    for (int k = 0; k < HH; k++) s += m[k] * W[k * OUTD + o];
    out[tid] = s;
}

// ---------------- launch ----------------
extern "C" void kernel_launch(void* const* d_in, const int* in_sizes, int n_in,
                              void* d_out, int out_size)
{
    const float* x     = (const float*)d_in[0];
    const int*   esrc  = (const int*)  d_in[1];
    const int*   edst  = (const int*)  d_in[2];
    const float* W_emb = (const float*)d_in[3];
    const float* b_emb = (const float*)d_in[4];
    const float* W_gcn = (const float*)d_in[5];
    const float* b_gcn = (const float*)d_in[6];
    const float* aW1   = (const float*)d_in[7];
    const float* ab1   = (const float*)d_in[8];
    const float* aW2   = (const float*)d_in[9];
    const float* ab2   = (const float*)d_in[10];
    const float* vW1   = (const float*)d_in[11];
    const float* vb1   = (const float*)d_in[12];
    const float* vW2   = (const float*)d_in[13];
    const float* vb2   = (const float*)d_in[14];
    const float* mW1   = (const float*)d_in[15];
    const float* mb1   = (const float*)d_in[16];
    const float* mW2   = (const float*)d_in[17];
    const float* mb2   = (const float*)d_in[18];
    const float* ew    = (const float*)d_in[19];
    float* out = (float*)d_out;

    float *h, *hw, *t1, *t, *mw, *vn, *vn2, *vn3, *gf, *m1;
    __nv_bfloat16 *wh, *wl;
    cudaGetSymbolAddress((void**)&h,   g_h);
    cudaGetSymbolAddress((void**)&hw,  g_hw);
    cudaGetSymbolAddress((void**)&t1,  g_t1);
    cudaGetSymbolAddress((void**)&t,   g_t);
    cudaGetSymbolAddress((void**)&mw,  g_mw);
    cudaGetSymbolAddress((void**)&vn,  g_vn);
    cudaGetSymbolAddress((void**)&vn2, g_vn2);
    cudaGetSymbolAddress((void**)&vn3, g_vn3);
    cudaGetSymbolAddress((void**)&gf,  g_gf);
    cudaGetSymbolAddress((void**)&m1,  g_m1);
    cudaGetSymbolAddress((void**)&wh,  g_wh);
    cudaGetSymbolAddress((void**)&wl,  g_wl);

    static bool attr_done = false;
    if (!attr_done) {
        cudaFuncSetAttribute(gemm_mma_kernel<false, true>,  cudaFuncAttributeMaxDynamicSharedMemorySize, GEMM_SMEM);
        cudaFuncSetAttribute(gemm_mma_kernel<false, false>, cudaFuncAttributeMaxDynamicSharedMemorySize, GEMM_SMEM);
        cudaFuncSetAttribute(gemm_mma_kernel<true,  true>,  cudaFuncAttributeMaxDynamicSharedMemorySize, GEMM_SMEM);
        attr_done = true;
    }

    dim3 t2d(16, 16);
    const int WS = 256 * 256;   // weight slot stride

    // launches 1-3
    split_all_kernel<<<dim3(256, 6), 256>>>(W_emb, W_gcn, aW1, aW2, vW1, vW2);
    zero_cursor_kernel<<<TOTAL_NODES / 256, 256>>>();
    fill_kernel<<<EE / 256, 256>>>(esrc, edst);

    // launch 4: first big GEMM (profiler lands here)
    // h = x @ W_emb + b_emb
    gemm_mma_kernel<false, true><<<dim3(HH / 128, TOTAL_NODES / 128), 256, GEMM_SMEM>>>(
        x, wh + 0 * WS, wl + 0 * WS, b_emb, h, TOTAL_NODES, HH, INF_);

    dinv_kernel<<<TOTAL_NODES / 256, 256>>>();

    // hw = h @ W_gcn
    gemm_mma_kernel<false, false><<<dim3(HH / 128, TOTAL_NODES / 128), 256, GEMM_SMEM>>>(
        h, wh + 1 * WS, wl + 1 * WS, nullptr, hw, TOTAL_NODES, HH, HH);
    // g = relu(agg + b_gcn)  (overwrites g_h)
    gather_gcn_kernel<<<TOTAL_NODES / 4, dim3(64, 4)>>>(b_gcn);

    // t = relu(g@aW1+ab1)@aW2+ab2
    gemm_mma_kernel<true, true><<<dim3(HH / 128, TOTAL_NODES / 128), 256, GEMM_SMEM>>>(
        h, wh + 2 * WS, wl + 2 * WS, ab1, t1, TOTAL_NODES, HH, HH);
    gemm_mma_kernel<false, true><<<dim3(HH / 128, TOTAL_NODES / 128), 256, GEMM_SMEM>>>(
        t1, wh + 3 * WS, wl + 3 * WS, ab2, t, TOTAL_NODES, HH, HH);

    // attention
    proto_kernel<<<BG, 256>>>();
    att_mw_kernel<<<TOTAL_NODES * 32 / 256, 256>>>(ew);

    // vn = mw^T @ g (per graph) via mma, then vn MLP
    vn_mma_kernel<<<dim3(2, BG), 256>>>(mw, h, vn);
    gemm_mma_kernel<true, true><<<dim3(HH / 128, BG * VV / 128), 256, GEMM_SMEM>>>(
        vn, wh + 4 * WS, wl + 4 * WS, vb1, vn2, BG * VV, HH, HH);
    gemm_mma_kernel<false, true><<<dim3(HH / 128, BG * VV / 128), 256, GEMM_SMEM>>>(
        vn2, wh + 5 * WS, wl + 5 * WS, vb2, vn3, BG * VV, HH, HH);

    // readout
    gf_kernel<<<BG, 256>>>();
    gemm_kernel<true, true><<<dim3(HH / 64, 1), t2d>>>(gf, mW1, mb1, m1, BG, HH, HH);
    out_kernel<<<1, 640>>>(mW2, mb2, out);
}

// round 12
// speedup vs baseline: 1.3072x; 1.0040x over previous
#include <cuda_runtime.h>
#include <cuda_bf16.h>
#include <math.h>
#include <cstdint>

// Problem constants (fixed shapes from the reference)
#define TOTAL_NODES 32768
#define BG   64
#define NN   512
#define VV   64
#define EE   1048576
#define INF_ 128
#define HH   256
#define OUTD 10
#define BUCKET 128   // fixed CSR bucket per node (avg deg 32, P(>128) ~ 0)

// ---------------- scratch (static device globals; no allocation) ----------------
__device__ float g_h  [TOTAL_NODES * HH];   // g (post-GCN)
__device__ float g_hw [TOTAL_NODES * HH];
__device__ float g_t1 [TOTAL_NODES * HH];
__device__ float g_t  [TOTAL_NODES * HH];
__device__ float g_proto[BG * HH];
__device__ float g_pn [BG];
__device__ float g_mw [BG * NN * VV];
__device__ float g_vn [BG * VV * HH];
__device__ float g_vn2[BG * VV * HH];
__device__ float g_vn3[BG * VV * HH];
__device__ float g_gf [BG * HH];
__device__ float g_m1 [BG * HH];
__device__ int   g_cursor[TOTAL_NODES];
__device__ float g_dinv  [TOTAL_NODES];
__device__ int   g_csr   [TOTAL_NODES * BUCKET];   // 16 MB fixed-stride buckets
// pre-split transposed weights: 6 slots of [N,K] bf16 (slot stride 256*256)
__device__ __nv_bfloat16 g_wh[6 * 256 * 256];
__device__ __nv_bfloat16 g_wl[6 * 256 * 256];

// ---------------- bucket CSR build (no scan) ----------------
__global__ void zero_cursor_kernel() {
    int i = blockIdx.x * blockDim.x + threadIdx.x;
    if (i < TOTAL_NODES) g_cursor[i] = 0;
}

__global__ void fill_kernel(const int* __restrict__ src, const int* __restrict__ dst) {
    int e = blockIdx.x * blockDim.x + threadIdx.x;
    if (e < EE) {
        int d = dst[e];
        int p = atomicAdd(&g_cursor[d], 1);
        g_csr[d * BUCKET + p] = src[e];
    }
}

__global__ void dinv_kernel() {
    int i = blockIdx.x * blockDim.x + threadIdx.x;
    if (i < TOTAL_NODES) g_dinv[i] = rsqrtf(1.0f + (float)g_cursor[i]);
}

// ---------------- fused weight split+transpose: all 6 weights in one launch ----------------
__global__ void split_all_kernel(const float* __restrict__ w0, const float* __restrict__ w1,
                                 const float* __restrict__ w2, const float* __restrict__ w3,
                                 const float* __restrict__ w4, const float* __restrict__ w5) {
    int slot = blockIdx.y;
    const float* W;
    switch (slot) {
        case 0: W = w0; break; case 1: W = w1; break; case 2: W = w2; break;
        case 3: W = w3; break; case 4: W = w4; break; default: W = w5; break;
    }
    int K = (slot == 0) ? INF_ : HH;
    int idx = blockIdx.x * 256 + threadIdx.x;
    if (idx >= K * HH) return;
    int k = idx / HH, n = idx % HH;
    float v = W[idx];
    __nv_bfloat16 hb = __float2bfloat16_rn(v);
    float r = v - __bfloat162float(hb);
    size_t o = (size_t)slot * (256 * 256) + (size_t)n * K + k;
    g_wh[o] = hb;
    g_wl[o] = __float2bfloat16_rn(r);
}

// ---------------- mma.sync bf16-split GEMM, double-buffered + cp.async + ldmatrix ----------------
#define MMA_BF16(d, a, b) \
    asm volatile("mma.sync.aligned.m16n8k16.row.col.f32.bf16.bf16.f32 " \
        "{%0,%1,%2,%3}, {%4,%5,%6,%7}, {%8,%9}, {%0,%1,%2,%3};" \
        : "+f"((d)[0]), "+f"((d)[1]), "+f"((d)[2]), "+f"((d)[3]) \
        : "r"((a)[0]), "r"((a)[1]), "r"((a)[2]), "r"((a)[3]), "r"((b)[0]), "r"((b)[1]))

#define LDSM4(r0, r1, r2, r3, addr) \
    asm volatile("ldmatrix.sync.aligned.m8n8.x4.shared.b16 {%0,%1,%2,%3}, [%4];" \
        : "=r"(r0), "=r"(r1), "=r"(r2), "=r"(r3) : "r"(addr))

#define APITCH 80                    // bytes per 32-bf16 row (64B data + 16B pad)
#define TILE_BYTES (128 * APITCH)    // 10240
#define BUF_BYTES  (4 * TILE_BYTES)  // Ah,Al,Bh,Bl per buffer
#define GEMM_SMEM  (2 * BUF_BYTES)   // 81920

__device__ __forceinline__ uint32_t smem_u32(const void* p) {
    uint32_t a;
    asm("{ .reg .u64 t; cvta.to.shared.u64 t, %1; cvt.u32.u64 %0, t; }" : "=r"(a) : "l"(p));
    return a;
}
#define CP_ASYNC16(saddr, gptr) \
    asm volatile("cp.async.cg.shared.global [%0], [%1], 16;" :: "r"(saddr), "l"(gptr))
#define CP_COMMIT() asm volatile("cp.async.commit_group;" ::: "memory")
#define CP_WAIT0()  asm volatile("cp.async.wait_group 0;" ::: "memory")

__device__ __forceinline__ uint32_t pack_split_hi(float a, float b,
                                                  __nv_bfloat16& ha, __nv_bfloat16& hb) {
    ha = __float2bfloat16_rn(a);
    hb = __float2bfloat16_rn(b);
    return (uint32_t)__bfloat16_as_ushort(ha) | ((uint32_t)__bfloat16_as_ushort(hb) << 16);
}
__device__ __forceinline__ uint32_t pack_lo(float a, float b, __nv_bfloat16 ha, __nv_bfloat16 hb) {
    __nv_bfloat16 la = __float2bfloat16_rn(a - __bfloat162float(ha));
    __nv_bfloat16 lb = __float2bfloat16_rn(b - __bfloat162float(hb));
    return (uint32_t)__bfloat16_as_ushort(la) | ((uint32_t)__bfloat16_as_ushort(lb) << 16);
}

template<bool RELU, bool BIAS>
__global__ void __launch_bounds__(256, 2) gemm_mma_kernel(
    const float* __restrict__ A,
    const __nv_bfloat16* __restrict__ Bh, const __nv_bfloat16* __restrict__ Bl,
    const float* __restrict__ bias, float* __restrict__ C,
    int M, int N, int K)
{
    extern __shared__ char smem[];
    const uint32_t sb32 = smem_u32(smem);

    const int tid = threadIdx.x;
    const int wid = tid >> 5, lane = tid & 31;
    const int warp_m = wid & 3;
    const int warp_n = wid >> 2;
    const int row0 = blockIdx.y * 128, col0 = blockIdx.x * 128;

    // ldmatrix per-lane address offsets (within a tile, before kb)
    const int mat = lane >> 3, r8 = lane & 7;
    // A: groups -> (rows+0/8 by mat&1, k half by mat>>1)
    const uint32_t aoff = (uint32_t)((warp_m * 32 + (mat & 1) * 8 + r8) * APITCH + (mat >> 1) * 16);
    // B: groups -> (nt within pair by mat>>1, k half by mat&1)
    const uint32_t boff = (uint32_t)((warp_n * 64 + (mat >> 1) * 8 + r8) * APITCH + (mat & 1) * 16);

    float acc[2][8][4];
#pragma unroll
    for (int i = 0; i < 2; i++)
#pragma unroll
        for (int j = 0; j < 8; j++)
#pragma unroll
            for (int q = 0; q < 4; q++) acc[i][j][q] = 0.f;

    const int nk = K >> 5;
    float4 pa[4];

    auto ldg_A = [&](int kc) {
#pragma unroll
        for (int it = 0; it < 4; it++) {
            int i = tid + it * 256;
            int r = i >> 3, kq = i & 7;
            pa[it] = *(const float4*)(A + (size_t)(row0 + r) * K + kc + kq * 4);
        }
    };
    auto sts_A = [&](int bb) {
        char* dAh = smem + bb * BUF_BYTES;
        char* dAl = dAh + TILE_BYTES;
#pragma unroll
        for (int it = 0; it < 4; it++) {
            int i = tid + it * 256;
            int r = i >> 3, kq = i & 7;
            float4 v = pa[it];
            __nv_bfloat16 h0, h1, h2, h3;
            uint2 uh, ul;
            uh.x = pack_split_hi(v.x, v.y, h0, h1);
            uh.y = pack_split_hi(v.z, v.w, h2, h3);
            ul.x = pack_lo(v.x, v.y, h0, h1);
            ul.y = pack_lo(v.z, v.w, h2, h3);
            *(uint2*)(dAh + r * APITCH + kq * 8) = uh;
            *(uint2*)(dAl + r * APITCH + kq * 8) = ul;
        }
    };
    auto cpasync_B = [&](int kc, int bb) {
        uint32_t dBh = sb32 + bb * BUF_BYTES + 2 * TILE_BYTES;
        uint32_t dBl = dBh + TILE_BYTES;
#pragma unroll
        for (int it = 0; it < 2; it++) {
            int i = tid + it * 256;
            int n = i >> 2, kq = i & 3;
            size_t goff = (size_t)(col0 + n) * K + kc + kq * 8;
            CP_ASYNC16(dBh + n * APITCH + kq * 16, Bh + goff);
            CP_ASYNC16(dBl + n * APITCH + kq * 16, Bl + goff);
        }
        CP_COMMIT();
    };

    ldg_A(0);
    cpasync_B(0, 0);
    sts_A(0);
    CP_WAIT0();
    __syncthreads();

    int buf = 0;
    for (int c = 0; c < nk; c++) {
        if (c + 1 < nk) {
            ldg_A((c + 1) << 5);
            cpasync_B((c + 1) << 5, buf ^ 1);
        }

        const uint32_t base = sb32 + buf * BUF_BYTES;
#pragma unroll
        for (int ks = 0; ks < 2; ks++) {
            const int kb = ks * 32;
            uint32_t ah[2][4], al[2][4];
            LDSM4(ah[0][0], ah[0][1], ah[0][2], ah[0][3], base + aoff + kb);
            LDSM4(ah[1][0], ah[1][1], ah[1][2], ah[1][3], base + aoff + kb + 16 * APITCH);
            LDSM4(al[0][0], al[0][1], al[0][2], al[0][3], base + TILE_BYTES + aoff + kb);
            LDSM4(al[1][0], al[1][1], al[1][2], al[1][3], base + TILE_BYTES + aoff + kb + 16 * APITCH);
#pragma unroll
            for (int p = 0; p < 4; p++) {
                uint32_t bq = base + 2 * TILE_BYTES + boff + kb + p * 16 * APITCH;
                uint32_t bhv[4], blv[4];
                LDSM4(bhv[0], bhv[1], bhv[2], bhv[3], bq);
                LDSM4(blv[0], blv[1], blv[2], blv[3], bq + TILE_BYTES);
#pragma unroll
                for (int sub = 0; sub < 2; sub++) {
                    uint32_t bh2[2] = {bhv[2 * sub], bhv[2 * sub + 1]};
                    uint32_t bl2[2] = {blv[2 * sub], blv[2 * sub + 1]};
                    const int nt = 2 * p + sub;
#pragma unroll
                    for (int mt = 0; mt < 2; mt++) {
                        MMA_BF16(acc[mt][nt], ah[mt], bh2);
                        MMA_BF16(acc[mt][nt], ah[mt], bl2);
                        MMA_BF16(acc[mt][nt], al[mt], bh2);
                    }
                }
            }
        }

        if (c + 1 < nk) {
            sts_A(buf ^ 1);
            CP_WAIT0();
        }
        __syncthreads();
        buf ^= 1;
    }

#pragma unroll
    for (int mt = 0; mt < 2; mt++) {
        int r0 = row0 + warp_m * 32 + mt * 16 + (lane >> 2);
#pragma unroll
        for (int nt = 0; nt < 8; nt++) {
            int c = col0 + warp_n * 64 + nt * 8 + (lane & 3) * 2;
            float v0 = acc[mt][nt][0], v1 = acc[mt][nt][1];
            float v2 = acc[mt][nt][2], v3 = acc[mt][nt][3];
            if (BIAS) {
                float b0 = bias[c], b1 = bias[c + 1];
                v0 += b0; v1 += b1; v2 += b0; v3 += b1;
            }
            if (RELU) {
                v0 = fmaxf(v0, 0.f); v1 = fmaxf(v1, 0.f);
                v2 = fmaxf(v2, 0.f); v3 = fmaxf(v3, 0.f);
            }
            *(float2*)(C + (size_t)r0 * N + c) = make_float2(v0, v1);
            *(float2*)(C + (size_t)(r0 + 8) * N + c) = make_float2(v2, v3);
        }
    }
}

// ---------------- vn mma GEMM: vn[b] = mw[b]^T (64x512) @ g[b] (512x256) ----------------
__global__ void __launch_bounds__(256) vn_mma_kernel(
    const float* __restrict__ mw, const float* __restrict__ gfeat, float* __restrict__ vn)
{
    __shared__ __align__(16) char sAh[64 * APITCH];
    __shared__ __align__(16) char sAl[64 * APITCH];
    __shared__ __align__(16) char sBh[128 * APITCH];
    __shared__ __align__(16) char sBl[128 * APITCH];

    const int b = blockIdx.y;
    const int col0 = blockIdx.x * 128;
    const float* mwb = mw + (size_t)b * NN * VV;
    const float* gb  = gfeat + (size_t)b * NN * HH;
    float* vnb = vn + (size_t)b * VV * HH;

    const int tid = threadIdx.x;
    const int wid = tid >> 5, lane = tid & 31;
    const int warp_m = wid & 1;
    const int warp_n = wid >> 1;
    const int lr = lane >> 2;
    const int lk4 = (lane & 3) * 4;

    float acc[2][4][4];
#pragma unroll
    for (int i = 0; i < 2; i++)
#pragma unroll
        for (int j = 0; j < 4; j++)
#pragma unroll
            for (int q = 0; q < 4; q++) acc[i][j][q] = 0.f;

    for (int kc = 0; kc < NN; kc += 32) {
#pragma unroll
        for (int it = 0; it < 4; it++) {
            int i = tid + it * 256;
            int v = i & 63, kp = i >> 6;
            float x0 = mwb[(size_t)(kc + 2 * kp) * VV + v];
            float x1 = mwb[(size_t)(kc + 2 * kp + 1) * VV + v];
            __nv_bfloat16 h0, h1;
            uint32_t uh = pack_split_hi(x0, x1, h0, h1);
            uint32_t ul = pack_lo(x0, x1, h0, h1);
            *(uint32_t*)(sAh + v * APITCH + kp * 4) = uh;
            *(uint32_t*)(sAl + v * APITCH + kp * 4) = ul;
        }
#pragma unroll
        for (int it = 0; it < 8; it++) {
            int i = tid + it * 256;
            int n = i & 127, kp = i >> 7;
            float x0 = gb[(size_t)(kc + 2 * kp) * HH + col0 + n];
            float x1 = gb[(size_t)(kc + 2 * kp + 1) * HH + col0 + n];
            __nv_bfloat16 h0, h1;
            uint32_t uh = pack_split_hi(x0, x1, h0, h1);
            uint32_t ul = pack_lo(x0, x1, h0, h1);
            *(uint32_t*)(sBh + n * APITCH + kp * 4) = uh;
            *(uint32_t*)(sBl + n * APITCH + kp * 4) = ul;
        }
        __syncthreads();

#pragma unroll
        for (int ks = 0; ks < 2; ks++) {
            const int kb = ks * 32;
            uint32_t ah[2][4], al[2][4];
#pragma unroll
            for (int mt = 0; mt < 2; mt++) {
                const char* base = sAh + (warp_m * 32 + mt * 16 + lr) * APITCH + kb + lk4;
                ah[mt][0] = *(const uint32_t*)base;
                ah[mt][1] = *(const uint32_t*)(base + 8 * APITCH);
                ah[mt][2] = *(const uint32_t*)(base + 16);
                ah[mt][3] = *(const uint32_t*)(base + 8 * APITCH + 16);
                const char* basel = sAl + (warp_m * 32 + mt * 16 + lr) * APITCH + kb + lk4;
                al[mt][0] = *(const uint32_t*)basel;
                al[mt][1] = *(const uint32_t*)(basel + 8 * APITCH);
                al[mt][2] = *(const uint32_t*)(basel + 16);
                al[mt][3] = *(const uint32_t*)(basel + 8 * APITCH + 16);
            }
#pragma unroll
            for (int nt = 0; nt < 4; nt++) {
                const char* bbase = sBh + (warp_n * 32 + nt * 8 + lr) * APITCH + kb + lk4;
                uint32_t bh[2], bl[2];
                bh[0] = *(const uint32_t*)bbase;
                bh[1] = *(const uint32_t*)(bbase + 16);
                const char* bbl = sBl + (warp_n * 32 + nt * 8 + lr) * APITCH + kb + lk4;
                bl[0] = *(const uint32_t*)bbl;
                bl[1] = *(const uint32_t*)(bbl + 16);
#pragma unroll
                for (int mt = 0; mt < 2; mt++) {
                    MMA_BF16(acc[mt][nt], ah[mt], bh);
                    MMA_BF16(acc[mt][nt], ah[mt], bl);
                    MMA_BF16(acc[mt][nt], al[mt], bh);
                }
            }
        }
        __syncthreads();
    }

#pragma unroll
    for (int mt = 0; mt < 2; mt++) {
        int r0 = warp_m * 32 + mt * 16 + lr;
#pragma unroll
        for (int nt = 0; nt < 4; nt++) {
            int c = col0 + warp_n * 32 + nt * 8 + (lane & 3) * 2;
            *(float2*)(vnb + (size_t)r0 * HH + c) = make_float2(acc[mt][nt][0], acc[mt][nt][1]);
            *(float2*)(vnb + (size_t)(r0 + 8) * HH + c) = make_float2(acc[mt][nt][2], acc[mt][nt][3]);
        }
    }
}

// ---------------- generic fp32 GEMM (64x64 tile) for tiny shapes ----------------
template<bool RELU, bool BIAS>
__global__ void gemm_kernel(const float* __restrict__ A, const float* __restrict__ B,
                            const float* __restrict__ bias, float* __restrict__ C,
                            int M, int N, int K)
{
    __shared__ float As[16][68];
    __shared__ float Bs[16][68];
    const int tx = threadIdx.x, ty = threadIdx.y;
    const int tid = ty * 16 + tx;
    const int row0 = blockIdx.y * 64, col0 = blockIdx.x * 64;
    float acc[4][4] = {};
    for (int k0 = 0; k0 < K; k0 += 16) {
#pragma unroll
        for (int i = tid; i < 1024; i += 256) {
            int m = i >> 4, kk = i & 15;
            As[kk][m] = (row0 + m < M) ? A[(size_t)(row0 + m) * K + k0 + kk] : 0.0f;
        }
#pragma unroll
        for (int i = tid; i < 1024; i += 256) {
            int kk = i >> 6, n = i & 63;
            Bs[kk][n] = B[(size_t)(k0 + kk) * N + col0 + n];
        }
        __syncthreads();
#pragma unroll
        for (int kk = 0; kk < 16; kk++) {
            float4 a = *(const float4*)&As[kk][ty * 4];
            float4 b = *(const float4*)&Bs[kk][tx * 4];
            float av[4] = {a.x, a.y, a.z, a.w};
            float bv[4] = {b.x, b.y, b.z, b.w};
#pragma unroll
            for (int i = 0; i < 4; i++)
#pragma unroll
                for (int j = 0; j < 4; j++)
                    acc[i][j] += av[i] * bv[j];
        }
        __syncthreads();
    }
#pragma unroll
    for (int i = 0; i < 4; i++) {
        int r = row0 + ty * 4 + i;
        if (r >= M) continue;
#pragma unroll
        for (int j = 0; j < 4; j++) {
            int c = col0 + tx * 4 + j;
            float v = acc[i][j];
            if (BIAS) v += bias[c];
            if (RELU) v = fmaxf(v, 0.0f);
            C[(size_t)r * N + c] = v;
        }
    }
}

// ---------------- GCN gather (bucket CSR, MLP=4 unrolled) + bias + relu ----------------
__global__ void gather_gcn_kernel(const float* __restrict__ bgcn) {
    int node = blockIdx.x * 4 + threadIdx.y;
    int t = threadIdx.x;              // 0..63
    const float4* hw4 = (const float4*)g_hw;
    const int* csr = g_csr + node * BUCKET;
    int deg = g_cursor[node];
    float di = g_dinv[node];
    float4 acc = make_float4(0.f, 0.f, 0.f, 0.f);
    int e = 0;
    for (; e + 4 <= deg; e += 4) {
        int s0 = csr[e], s1 = csr[e + 1], s2 = csr[e + 2], s3 = csr[e + 3];
        float c0 = g_dinv[s0] * di, c1 = g_dinv[s1] * di;
        float c2 = g_dinv[s2] * di, c3 = g_dinv[s3] * di;
        float4 v0 = hw4[(size_t)s0 * 64 + t];
        float4 v1 = hw4[(size_t)s1 * 64 + t];
        float4 v2 = hw4[(size_t)s2 * 64 + t];
        float4 v3 = hw4[(size_t)s3 * 64 + t];
        acc.x += v0.x * c0 + v1.x * c1 + v2.x * c2 + v3.x * c3;
        acc.y += v0.y * c0 + v1.y * c1 + v2.y * c2 + v3.y * c3;
        acc.z += v0.z * c0 + v1.z * c1 + v2.z * c2 + v3.z * c3;
        acc.w += v0.w * c0 + v1.w * c1 + v2.w * c2 + v3.w * c3;
    }
    for (; e < deg; e++) {
        int s = csr[e];
        float coef = g_dinv[s] * di;
        float4 v = hw4[(size_t)s * 64 + t];
        acc.x += v.x * coef; acc.y += v.y * coef;
        acc.z += v.z * coef; acc.w += v.w * coef;
    }
    float cs = di * di;
    float4 v = hw4[(size_t)node * 64 + t];
    acc.x += v.x * cs; acc.y += v.y * cs; acc.z += v.z * cs; acc.w += v.w * cs;
    float4 bb = ((const float4*)bgcn)[t];
    acc.x = fmaxf(acc.x + bb.x, 0.f);
    acc.y = fmaxf(acc.y + bb.y, 0.f);
    acc.z = fmaxf(acc.z + bb.z, 0.f);
    acc.w = fmaxf(acc.w + bb.w, 0.f);
    ((float4*)g_h)[(size_t)node * 64 + t] = acc;
}

// ---------------- proto = mean_n t, pn = ||proto|| ----------------
__global__ void proto_kernel() {
    int b = blockIdx.x;
    int h = threadIdx.x;   // 256
    const float* tb = g_t + (size_t)b * NN * HH;
    float s = 0.f;
    for (int n = 0; n < NN; n++) s += tb[(size_t)n * HH + h];
    s *= (1.0f / NN);
    g_proto[b * HH + h] = s;
    __shared__ float red[256];
    red[h] = s * s;
    __syncthreads();
    for (int off = 128; off > 0; off >>= 1) {
        if (h < off) red[h] += red[h + off];
        __syncthreads();
    }
    if (h == 0) g_pn[b] = fmaxf(sqrtf(red[0]), 1e-8f);
}

// ---------------- fused attention + mw (warp per node) ----------------
__global__ void att_mw_kernel(const float* __restrict__ ew) {
    int w = (blockIdx.x * blockDim.x + threadIdx.x) >> 5;
    int lane = threadIdx.x & 31;
    if (w >= TOTAL_NODES) return;
    int b = w >> 9;
    const float* tr = g_t + (size_t)w * HH;
    const float* pr = g_proto + b * HH;
    float dot = 0.f, nrm = 0.f;
    for (int j = lane; j < HH; j += 32) {
        float v = tr[j];
        dot += v * pr[j];
        nrm += v * v;
    }
#pragma unroll
    for (int off = 16; off; off >>= 1) {
        dot += __shfl_xor_sync(0xffffffffu, dot, off);
        nrm += __shfl_xor_sync(0xffffffffu, nrm, off);
    }
    float tn = fmaxf(sqrtf(nrm), 1e-8f);
    float sim = dot / (tn * g_pn[b]);
    float a = 0.5f * (1.0f + sim);

    const float* e = ew + (size_t)w * VV;
    float v0 = e[lane] * a;
    float v1 = e[lane + 32] * a;
    float rs = v0 + v1;
#pragma unroll
    for (int off = 16; off; off >>= 1) rs += __shfl_xor_sync(0xffffffffu, rs, off);
    float sc = (rs == 0.0f) ? 1.0f : (1.0f / rs);
    float* m = g_mw + (size_t)w * VV;
    m[lane]      = v0 * sc;
    m[lane + 32] = v1 * sc;
}

// ---------------- gf = mean over V ----------------
__global__ void gf_kernel() {
    int b = blockIdx.x, h = threadIdx.x;
    const float* v = g_vn3 + (size_t)b * VV * HH;
    float s = 0.f;
    for (int i = 0; i < VV; i++) s += v[i * HH + h];
    g_gf[b * HH + h] = s * (1.0f / VV);
}

// ---------------- out = m1 @ mW2 + mb2 ----------------
__global__ void out_kernel(const float* __restrict__ W, const float* __restrict__ bias,
                           float* __restrict__ out)
{
    int tid = threadIdx.x;
    if (tid >= BG * OUTD) return;
    int b = tid / OUTD, o = tid % OUTD;
    const float* m = g_m1 + b * HH;
    float s = bias[o];
    for (int k = 0; k < HH; k++) s += m[k] * W[k * OUTD + o];
    out[tid] = s;
}

// ---------------- launch ----------------
extern "C" void kernel_launch(void* const* d_in, const int* in_sizes, int n_in,
                              void* d_out, int out_size)
{
    const float* x     = (const float*)d_in[0];
    const int*   esrc  = (const int*)  d_in[1];
    const int*   edst  = (const int*)  d_in[2];
    const float* W_emb = (const float*)d_in[3];
    const float* b_emb = (const float*)d_in[4];
    const float* W_gcn = (const float*)d_in[5];
    const float* b_gcn = (const float*)d_in[6];
    const float* aW1   = (const float*)d_in[7];
    const float* ab1   = (const float*)d_in[8];
    const float* aW2   = (const float*)d_in[9];
    const float* ab2   = (const float*)d_in[10];
    const float* vW1   = (const float*)d_in[11];
    const float* vb1   = (const float*)d_in[12];
    const float* vW2   = (const float*)d_in[13];
    const float* vb2   = (const float*)d_in[14];
    const float* mW1   = (const float*)d_in[15];
    const float* mb1   = (const float*)d_in[16];
    const float* mW2   = (const float*)d_in[17];
    const float* mb2   = (const float*)d_in[18];
    const float* ew    = (const float*)d_in[19];
    float* out = (float*)d_out;

    float *h, *hw, *t1, *t, *mw, *vn, *vn2, *vn3, *gf, *m1;
    __nv_bfloat16 *wh, *wl;
    cudaGetSymbolAddress((void**)&h,   g_h);
    cudaGetSymbolAddress((void**)&hw,  g_hw);
    cudaGetSymbolAddress((void**)&t1,  g_t1);
    cudaGetSymbolAddress((void**)&t,   g_t);
    cudaGetSymbolAddress((void**)&mw,  g_mw);
    cudaGetSymbolAddress((void**)&vn,  g_vn);
    cudaGetSymbolAddress((void**)&vn2, g_vn2);
    cudaGetSymbolAddress((void**)&vn3, g_vn3);
    cudaGetSymbolAddress((void**)&gf,  g_gf);
    cudaGetSymbolAddress((void**)&m1,  g_m1);
    cudaGetSymbolAddress((void**)&wh,  g_wh);
    cudaGetSymbolAddress((void**)&wl,  g_wl);

    static bool attr_done = false;
    if (!attr_done) {
        cudaFuncSetAttribute(gemm_mma_kernel<false, true>,  cudaFuncAttributeMaxDynamicSharedMemorySize, GEMM_SMEM);
        cudaFuncSetAttribute(gemm_mma_kernel<false, false>, cudaFuncAttributeMaxDynamicSharedMemorySize, GEMM_SMEM);
        cudaFuncSetAttribute(gemm_mma_kernel<true,  true>,  cudaFuncAttributeMaxDynamicSharedMemorySize, GEMM_SMEM);
        attr_done = true;
    }

    dim3 t2d(16, 16);
    const int WS = 256 * 256;   // weight slot stride

    // launches 1-3
    split_all_kernel<<<dim3(256, 6), 256>>>(W_emb, W_gcn, aW1, aW2, vW1, vW2);
    zero_cursor_kernel<<<TOTAL_NODES / 256, 256>>>();
    fill_kernel<<<EE / 256, 256>>>(esrc, edst);

    // launch 4: first big GEMM (profiler lands here)
    gemm_mma_kernel<false, true><<<dim3(HH / 128, TOTAL_NODES / 128), 256, GEMM_SMEM>>>(
        x, wh + 0 * WS, wl + 0 * WS, b_emb, h, TOTAL_NODES, HH, INF_);

    dinv_kernel<<<TOTAL_NODES / 256, 256>>>();

    // hw = h @ W_gcn
    gemm_mma_kernel<false, false><<<dim3(HH / 128, TOTAL_NODES / 128), 256, GEMM_SMEM>>>(
        h, wh + 1 * WS, wl + 1 * WS, nullptr, hw, TOTAL_NODES, HH, HH);
    // g = relu(agg + b_gcn)  (overwrites g_h)
    gather_gcn_kernel<<<TOTAL_NODES / 4, dim3(64, 4)>>>(b_gcn);

    // t = relu(g@aW1+ab1)@aW2+ab2
    gemm_mma_kernel<true, true><<<dim3(HH / 128, TOTAL_NODES / 128), 256, GEMM_SMEM>>>(
        h, wh + 2 * WS, wl + 2 * WS, ab1, t1, TOTAL_NODES, HH, HH);
    gemm_mma_kernel<false, true><<<dim3(HH / 128, TOTAL_NODES / 128), 256, GEMM_SMEM>>>(
        t1, wh + 3 * WS, wl + 3 * WS, ab2, t, TOTAL_NODES, HH, HH);

    // attention
    proto_kernel<<<BG, 256>>>();
    att_mw_kernel<<<TOTAL_NODES * 32 / 256, 256>>>(ew);

    // vn = mw^T @ g (per graph) via mma, then vn MLP
    vn_mma_kernel<<<dim3(2, BG), 256>>>(mw, h, vn);
    gemm_mma_kernel<true, true><<<dim3(HH / 128, BG * VV / 128), 256, GEMM_SMEM>>>(
        vn, wh + 4 * WS, wl + 4 * WS, vb1, vn2, BG * VV, HH, HH);
    gemm_mma_kernel<false, true><<<dim3(HH / 128, BG * VV / 128), 256, GEMM_SMEM>>>(
        vn2, wh + 5 * WS, wl + 5 * WS, vb2, vn3, BG * VV, HH, HH);

    // readout
    gf_kernel<<<BG, 256>>>();
    gemm_kernel<true, true><<<dim3(HH / 64, 1), t2d>>>(gf, mW1, mb1, m1, BG, HH, HH);
    out_kernel<<<1, 640>>>(mW2, mb2, out);
}

// round 13
// speedup vs baseline: 1.3803x; 1.0559x over previous
#include <cuda_runtime.h>
#include <cuda_bf16.h>
#include <math.h>
#include <cstdint>

// Problem constants (fixed shapes from the reference)
#define TOTAL_NODES 32768
#define BG   64
#define NN   512
#define VV   64
#define EE   1048576
#define INF_ 128
#define HH   256
#define OUTD 10
#define BUCKET 128   // fixed CSR bucket per node (avg deg 32, P(>128) ~ 0)

// ---------------- scratch (static device globals; no allocation) ----------------
__device__ float g_h  [TOTAL_NODES * HH];   // g (post-GCN)
__device__ float g_hw [TOTAL_NODES * HH];
__device__ float g_t1 [TOTAL_NODES * HH];
__device__ float g_t  [TOTAL_NODES * HH];
__device__ float g_proto[BG * HH];
__device__ float g_pn [BG];
__device__ float g_mw [BG * NN * VV];
__device__ float g_vn [BG * VV * HH];
__device__ float g_vn2[BG * VV * HH];
__device__ float g_vn3[BG * VV * HH];
__device__ float g_gf [BG * HH];
__device__ float g_m1 [BG * HH];
__device__ int   g_cursor[TOTAL_NODES];
__device__ float g_dinv  [TOTAL_NODES];
__device__ int   g_csr   [TOTAL_NODES * BUCKET];   // 16 MB fixed-stride buckets
// pre-split transposed weights: 6 slots of [N,K] bf16 (slot stride 256*256)
__device__ __nv_bfloat16 g_wh[6 * 256 * 256];
__device__ __nv_bfloat16 g_wl[6 * 256 * 256];

// ---------------- bucket CSR build (no scan) ----------------
__global__ void zero_cursor_kernel() {
    int i = blockIdx.x * blockDim.x + threadIdx.x;
    if (i < TOTAL_NODES) g_cursor[i] = 0;
}

__global__ void fill_kernel(const int* __restrict__ src, const int* __restrict__ dst) {
    int e = blockIdx.x * blockDim.x + threadIdx.x;
    if (e < EE) {
        int d = dst[e];
        int p = atomicAdd(&g_cursor[d], 1);
        g_csr[d * BUCKET + p] = src[e];
    }
}

__global__ void dinv_kernel() {
    int i = blockIdx.x * blockDim.x + threadIdx.x;
    if (i < TOTAL_NODES) g_dinv[i] = rsqrtf(1.0f + (float)g_cursor[i]);
}

// ---------------- fused weight split+transpose: all 6 weights in one launch ----------------
__global__ void split_all_kernel(const float* __restrict__ w0, const float* __restrict__ w1,
                                 const float* __restrict__ w2, const float* __restrict__ w3,
                                 const float* __restrict__ w4, const float* __restrict__ w5) {
    int slot = blockIdx.y;
    const float* W;
    switch (slot) {
        case 0: W = w0; break; case 1: W = w1; break; case 2: W = w2; break;
        case 3: W = w3; break; case 4: W = w4; break; default: W = w5; break;
    }
    int K = (slot == 0) ? INF_ : HH;
    int idx = blockIdx.x * 256 + threadIdx.x;
    if (idx >= K * HH) return;
    int k = idx / HH, n = idx % HH;
    float v = W[idx];
    __nv_bfloat16 hb = __float2bfloat16_rn(v);
    float r = v - __bfloat162float(hb);
    size_t o = (size_t)slot * (256 * 256) + (size_t)n * K + k;
    g_wh[o] = hb;
    g_wl[o] = __float2bfloat16_rn(r);
}

// ---------------- mma.sync bf16-split GEMM ----------------
// 64(M) x 128(N) CTA tile, BK=32, 8 warps (2x4), warp tile 32x32.
// Double-buffered, cp.async for B, ldmatrix fragments, 3 CTAs/SM.
#define MMA_BF16(d, a, b) \
    asm volatile("mma.sync.aligned.m16n8k16.row.col.f32.bf16.bf16.f32 " \
        "{%0,%1,%2,%3}, {%4,%5,%6,%7}, {%8,%9}, {%0,%1,%2,%3};" \
        : "+f"((d)[0]), "+f"((d)[1]), "+f"((d)[2]), "+f"((d)[3]) \
        : "r"((a)[0]), "r"((a)[1]), "r"((a)[2]), "r"((a)[3]), "r"((b)[0]), "r"((b)[1]))

#define LDSM4(r0, r1, r2, r3, addr) \
    asm volatile("ldmatrix.sync.aligned.m8n8.x4.shared.b16 {%0,%1,%2,%3}, [%4];" \
        : "=r"(r0), "=r"(r1), "=r"(r2), "=r"(r3) : "r"(addr))

#define APITCH 80                     // bytes per 32-bf16 row (64B data + 16B pad)
#define A_TILE (64 * APITCH)          // 5120
#define B_TILE (128 * APITCH)         // 10240
#define BUF_BYTES (2 * A_TILE + 2 * B_TILE)   // 30720: Ah, Al, Bh, Bl
#define OFF_AL  A_TILE
#define OFF_BH  (2 * A_TILE)
#define OFF_BL  (2 * A_TILE + B_TILE)
#define GEMM_SMEM (2 * BUF_BYTES)     // 61440

__device__ __forceinline__ uint32_t smem_u32(const void* p) {
    uint32_t a;
    asm("{ .reg .u64 t; cvta.to.shared.u64 t, %1; cvt.u32.u64 %0, t; }" : "=r"(a) : "l"(p));
    return a;
}
#define CP_ASYNC16(saddr, gptr) \
    asm volatile("cp.async.cg.shared.global [%0], [%1], 16;" :: "r"(saddr), "l"(gptr))
#define CP_COMMIT() asm volatile("cp.async.commit_group;" ::: "memory")
#define CP_WAIT0()  asm volatile("cp.async.wait_group 0;" ::: "memory")

__device__ __forceinline__ uint32_t pack_split_hi(float a, float b,
                                                  __nv_bfloat16& ha, __nv_bfloat16& hb) {
    ha = __float2bfloat16_rn(a);
    hb = __float2bfloat16_rn(b);
    return (uint32_t)__bfloat16_as_ushort(ha) | ((uint32_t)__bfloat16_as_ushort(hb) << 16);
}
__device__ __forceinline__ uint32_t pack_lo(float a, float b, __nv_bfloat16 ha, __nv_bfloat16 hb) {
    __nv_bfloat16 la = __float2bfloat16_rn(a - __bfloat162float(ha));
    __nv_bfloat16 lb = __float2bfloat16_rn(b - __bfloat162float(hb));
    return (uint32_t)__bfloat16_as_ushort(la) | ((uint32_t)__bfloat16_as_ushort(lb) << 16);
}

template<bool RELU, bool BIAS>
__global__ void __launch_bounds__(256, 3) gemm_mma_kernel(
    const float* __restrict__ A,
    const __nv_bfloat16* __restrict__ Bh, const __nv_bfloat16* __restrict__ Bl,
    const float* __restrict__ bias, float* __restrict__ C,
    int M, int N, int K)
{
    extern __shared__ char smem[];
    const uint32_t sb32 = smem_u32(smem);

    const int tid = threadIdx.x;
    const int wid = tid >> 5, lane = tid & 31;
    const int warp_m = wid & 1;       // 2 x 32 rows
    const int warp_n = wid >> 1;      // 4 x 32 cols
    const int row0 = blockIdx.y * 64, col0 = blockIdx.x * 128;

    // ldmatrix per-lane address offsets (within a tile, before kb)
    const int mat = lane >> 3, r8 = lane & 7;
    const uint32_t aoff = (uint32_t)((warp_m * 32 + (mat & 1) * 8 + r8) * APITCH + (mat >> 1) * 16);
    const uint32_t boff = (uint32_t)((warp_n * 32 + (mat >> 1) * 8 + r8) * APITCH + (mat & 1) * 16);

    float acc[2][4][4];
#pragma unroll
    for (int i = 0; i < 2; i++)
#pragma unroll
        for (int j = 0; j < 4; j++)
#pragma unroll
            for (int q = 0; q < 4; q++) acc[i][j][q] = 0.f;

    const int nk = K >> 5;
    float4 pa[2];

    auto ldg_A = [&](int kc) {
#pragma unroll
        for (int it = 0; it < 2; it++) {
            int i = tid + it * 256;       // 0..511
            int r = i >> 3, kq = i & 7;
            pa[it] = *(const float4*)(A + (size_t)(row0 + r) * K + kc + kq * 4);
        }
    };
    auto sts_A = [&](int bb) {
        char* dAh = smem + bb * BUF_BYTES;
        char* dAl = dAh + OFF_AL;
#pragma unroll
        for (int it = 0; it < 2; it++) {
            int i = tid + it * 256;
            int r = i >> 3, kq = i & 7;
            float4 v = pa[it];
            __nv_bfloat16 h0, h1, h2, h3;
            uint2 uh, ul;
            uh.x = pack_split_hi(v.x, v.y, h0, h1);
            uh.y = pack_split_hi(v.z, v.w, h2, h3);
            ul.x = pack_lo(v.x, v.y, h0, h1);
            ul.y = pack_lo(v.z, v.w, h2, h3);
            *(uint2*)(dAh + r * APITCH + kq * 8) = uh;
            *(uint2*)(dAl + r * APITCH + kq * 8) = ul;
        }
    };
    auto cpasync_B = [&](int kc, int bb) {
        uint32_t dBh = sb32 + bb * BUF_BYTES + OFF_BH;
        uint32_t dBl = sb32 + bb * BUF_BYTES + OFF_BL;
#pragma unroll
        for (int it = 0; it < 2; it++) {
            int i = tid + it * 256;       // 0..511
            int n = i >> 2, kq = i & 3;
            size_t goff = (size_t)(col0 + n) * K + kc + kq * 8;
            CP_ASYNC16(dBh + n * APITCH + kq * 16, Bh + goff);
            CP_ASYNC16(dBl + n * APITCH + kq * 16, Bl + goff);
        }
        CP_COMMIT();
    };

    ldg_A(0);
    cpasync_B(0, 0);
    sts_A(0);
    CP_WAIT0();
    __syncthreads();

    int buf = 0;
    for (int c = 0; c < nk; c++) {
        if (c + 1 < nk) {
            ldg_A((c + 1) << 5);
            cpasync_B((c + 1) << 5, buf ^ 1);
        }

        const uint32_t base = sb32 + buf * BUF_BYTES;
#pragma unroll
        for (int ks = 0; ks < 2; ks++) {
            const int kb = ks * 32;
            uint32_t ah[2][4], al[2][4];
            LDSM4(ah[0][0], ah[0][1], ah[0][2], ah[0][3], base + aoff + kb);
            LDSM4(ah[1][0], ah[1][1], ah[1][2], ah[1][3], base + aoff + kb + 16 * APITCH);
            LDSM4(al[0][0], al[0][1], al[0][2], al[0][3], base + OFF_AL + aoff + kb);
            LDSM4(al[1][0], al[1][1], al[1][2], al[1][3], base + OFF_AL + aoff + kb + 16 * APITCH);
#pragma unroll
            for (int p = 0; p < 2; p++) {
                uint32_t bq = base + OFF_BH + boff + kb + p * 16 * APITCH;
                uint32_t bhv[4], blv[4];
                LDSM4(bhv[0], bhv[1], bhv[2], bhv[3], bq);
                LDSM4(blv[0], blv[1], blv[2], blv[3], bq + B_TILE);
#pragma unroll
                for (int sub = 0; sub < 2; sub++) {
                    uint32_t bh2[2] = {bhv[2 * sub], bhv[2 * sub + 1]};
                    uint32_t bl2[2] = {blv[2 * sub], blv[2 * sub + 1]};
                    const int nt = 2 * p + sub;
#pragma unroll
                    for (int mt = 0; mt < 2; mt++) {
                        MMA_BF16(acc[mt][nt], ah[mt], bh2);
                        MMA_BF16(acc[mt][nt], ah[mt], bl2);
                        MMA_BF16(acc[mt][nt], al[mt], bh2);
                    }
                }
            }
        }

        if (c + 1 < nk) {
            sts_A(buf ^ 1);
            CP_WAIT0();
        }
        __syncthreads();
        buf ^= 1;
    }

#pragma unroll
    for (int mt = 0; mt < 2; mt++) {
        int r0 = row0 + warp_m * 32 + mt * 16 + (lane >> 2);
#pragma unroll
        for (int nt = 0; nt < 4; nt++) {
            int c = col0 + warp_n * 32 + nt * 8 + (lane & 3) * 2;
            float v0 = acc[mt][nt][0], v1 = acc[mt][nt][1];
            float v2 = acc[mt][nt][2], v3 = acc[mt][nt][3];
            if (BIAS) {
                float b0 = bias[c], b1 = bias[c + 1];
                v0 += b0; v1 += b1; v2 += b0; v3 += b1;
            }
            if (RELU) {
                v0 = fmaxf(v0, 0.f); v1 = fmaxf(v1, 0.f);
                v2 = fmaxf(v2, 0.f); v3 = fmaxf(v3, 0.f);
            }
            *(float2*)(C + (size_t)r0 * N + c) = make_float2(v0, v1);
            *(float2*)(C + (size_t)(r0 + 8) * N + c) = make_float2(v2, v3);
        }
    }
}

// ---------------- vn mma GEMM: vn[b] = mw[b]^T (64x512) @ g[b] (512x256) ----------------
__global__ void __launch_bounds__(256) vn_mma_kernel(
    const float* __restrict__ mw, const float* __restrict__ gfeat, float* __restrict__ vn)
{
    __shared__ __align__(16) char sAh[64 * APITCH];
    __shared__ __align__(16) char sAl[64 * APITCH];
    __shared__ __align__(16) char sBh[128 * APITCH];
    __shared__ __align__(16) char sBl[128 * APITCH];

    const int b = blockIdx.y;
    const int col0 = blockIdx.x * 128;
    const float* mwb = mw + (size_t)b * NN * VV;
    const float* gb  = gfeat + (size_t)b * NN * HH;
    float* vnb = vn + (size_t)b * VV * HH;

    const int tid = threadIdx.x;
    const int wid = tid >> 5, lane = tid & 31;
    const int warp_m = wid & 1;
    const int warp_n = wid >> 1;
    const int lr = lane >> 2;
    const int lk4 = (lane & 3) * 4;

    float acc[2][4][4];
#pragma unroll
    for (int i = 0; i < 2; i++)
#pragma unroll
        for (int j = 0; j < 4; j++)
#pragma unroll
            for (int q = 0; q < 4; q++) acc[i][j][q] = 0.f;

    for (int kc = 0; kc < NN; kc += 32) {
#pragma unroll
        for (int it = 0; it < 4; it++) {
            int i = tid + it * 256;
            int v = i & 63, kp = i >> 6;
            float x0 = mwb[(size_t)(kc + 2 * kp) * VV + v];
            float x1 = mwb[(size_t)(kc + 2 * kp + 1) * VV + v];
            __nv_bfloat16 h0, h1;
            uint32_t uh = pack_split_hi(x0, x1, h0, h1);
            uint32_t ul = pack_lo(x0, x1, h0, h1);
            *(uint32_t*)(sAh + v * APITCH + kp * 4) = uh;
            *(uint32_t*)(sAl + v * APITCH + kp * 4) = ul;
        }
#pragma unroll
        for (int it = 0; it < 8; it++) {
            int i = tid + it * 256;
            int n = i & 127, kp = i >> 7;
            float x0 = gb[(size_t)(kc + 2 * kp) * HH + col0 + n];
            float x1 = gb[(size_t)(kc + 2 * kp + 1) * HH + col0 + n];
            __nv_bfloat16 h0, h1;
            uint32_t uh = pack_split_hi(x0, x1, h0, h1);
            uint32_t ul = pack_lo(x0, x1, h0, h1);
            *(uint32_t*)(sBh + n * APITCH + kp * 4) = uh;
            *(uint32_t*)(sBl + n * APITCH + kp * 4) = ul;
        }
        __syncthreads();

#pragma unroll
        for (int ks = 0; ks < 2; ks++) {
            const int kb = ks * 32;
            uint32_t ah[2][4], al[2][4];
#pragma unroll
            for (int mt = 0; mt < 2; mt++) {
                const char* base = sAh + (warp_m * 32 + mt * 16 + lr) * APITCH + kb + lk4;
                ah[mt][0] = *(const uint32_t*)base;
                ah[mt][1] = *(const uint32_t*)(base + 8 * APITCH);
                ah[mt][2] = *(const uint32_t*)(base + 16);
                ah[mt][3] = *(const uint32_t*)(base + 8 * APITCH + 16);
                const char* basel = sAl + (warp_m * 32 + mt * 16 + lr) * APITCH + kb + lk4;
                al[mt][0] = *(const uint32_t*)basel;
                al[mt][1] = *(const uint32_t*)(basel + 8 * APITCH);
                al[mt][2] = *(const uint32_t*)(basel + 16);
                al[mt][3] = *(const uint32_t*)(basel + 8 * APITCH + 16);
            }
#pragma unroll
            for (int nt = 0; nt < 4; nt++) {
                const char* bbase = sBh + (warp_n * 32 + nt * 8 + lr) * APITCH + kb + lk4;
                uint32_t bh[2], bl[2];
                bh[0] = *(const uint32_t*)bbase;
                bh[1] = *(const uint32_t*)(bbase + 16);
                const char* bbl = sBl + (warp_n * 32 + nt * 8 + lr) * APITCH + kb + lk4;
                bl[0] = *(const uint32_t*)bbl;
                bl[1] = *(const uint32_t*)(bbl + 16);
#pragma unroll
                for (int mt = 0; mt < 2; mt++) {
                    MMA_BF16(acc[mt][nt], ah[mt], bh);
                    MMA_BF16(acc[mt][nt], ah[mt], bl);
                    MMA_BF16(acc[mt][nt], al[mt], bh);
                }
            }
        }
        __syncthreads();
    }

#pragma unroll
    for (int mt = 0; mt < 2; mt++) {
        int r0 = warp_m * 32 + mt * 16 + lr;
#pragma unroll
        for (int nt = 0; nt < 4; nt++) {
            int c = col0 + warp_n * 32 + nt * 8 + (lane & 3) * 2;
            *(float2*)(vnb + (size_t)r0 * HH + c) = make_float2(acc[mt][nt][0], acc[mt][nt][1]);
            *(float2*)(vnb + (size_t)(r0 + 8) * HH + c) = make_float2(acc[mt][nt][2], acc[mt][nt][3]);
        }
    }
}

// ---------------- generic fp32 GEMM (64x64 tile) for tiny shapes ----------------
template<bool RELU, bool BIAS>
__global__ void gemm_kernel(const float* __restrict__ A, const float* __restrict__ B,
                            const float* __restrict__ bias, float* __restrict__ C,
                            int M, int N, int K)
{
    __shared__ float As[16][68];
    __shared__ float Bs[16][68];
    const int tx = threadIdx.x, ty = threadIdx.y;
    const int tid = ty * 16 + tx;
    const int row0 = blockIdx.y * 64, col0 = blockIdx.x * 64;
    float acc[4][4] = {};
    for (int k0 = 0; k0 < K; k0 += 16) {
#pragma unroll
        for (int i = tid; i < 1024; i += 256) {
            int m = i >> 4, kk = i & 15;
            As[kk][m] = (row0 + m < M) ? A[(size_t)(row0 + m) * K + k0 + kk] : 0.0f;
        }
#pragma unroll
        for (int i = tid; i < 1024; i += 256) {
            int kk = i >> 6, n = i & 63;
            Bs[kk][n] = B[(size_t)(k0 + kk) * N + col0 + n];
        }
        __syncthreads();
#pragma unroll
        for (int kk = 0; kk < 16; kk++) {
            float4 a = *(const float4*)&As[kk][ty * 4];
            float4 b = *(const float4*)&Bs[kk][tx * 4];
            float av[4] = {a.x, a.y, a.z, a.w};
            float bv[4] = {b.x, b.y, b.z, b.w};
#pragma unroll
            for (int i = 0; i < 4; i++)
#pragma unroll
                for (int j = 0; j < 4; j++)
                    acc[i][j] += av[i] * bv[j];
        }
        __syncthreads();
    }
#pragma unroll
    for (int i = 0; i < 4; i++) {
        int r = row0 + ty * 4 + i;
        if (r >= M) continue;
#pragma unroll
        for (int j = 0; j < 4; j++) {
            int c = col0 + tx * 4 + j;
            float v = acc[i][j];
            if (BIAS) v += bias[c];
            if (RELU) v = fmaxf(v, 0.0f);
            C[(size_t)r * N + c] = v;
        }
    }
}

// ---------------- GCN gather (bucket CSR, MLP=4 unrolled) + bias + relu ----------------
__global__ void gather_gcn_kernel(const float* __restrict__ bgcn) {
    int node = blockIdx.x * 4 + threadIdx.y;
    int t = threadIdx.x;              // 0..63
    const float4* hw4 = (const float4*)g_hw;
    const int* csr = g_csr + node * BUCKET;
    int deg = g_cursor[node];
    float di = g_dinv[node];
    float4 acc = make_float4(0.f, 0.f, 0.f, 0.f);
    int e = 0;
    for (; e + 4 <= deg; e += 4) {
        int s0 = csr[e], s1 = csr[e + 1], s2 = csr[e + 2], s3 = csr[e + 3];
        float c0 = g_dinv[s0] * di, c1 = g_dinv[s1] * di;
        float c2 = g_dinv[s2] * di, c3 = g_dinv[s3] * di;
        float4 v0 = hw4[(size_t)s0 * 64 + t];
        float4 v1 = hw4[(size_t)s1 * 64 + t];
        float4 v2 = hw4[(size_t)s2 * 64 + t];
        float4 v3 = hw4[(size_t)s3 * 64 + t];
        acc.x += v0.x * c0 + v1.x * c1 + v2.x * c2 + v3.x * c3;
        acc.y += v0.y * c0 + v1.y * c1 + v2.y * c2 + v3.y * c3;
        acc.z += v0.z * c0 + v1.z * c1 + v2.z * c2 + v3.z * c3;
        acc.w += v0.w * c0 + v1.w * c1 + v2.w * c2 + v3.w * c3;
    }
    for (; e < deg; e++) {
        int s = csr[e];
        float coef = g_dinv[s] * di;
        float4 v = hw4[(size_t)s * 64 + t];
        acc.x += v.x * coef; acc.y += v.y * coef;
        acc.z += v.z * coef; acc.w += v.w * coef;
    }
    float cs = di * di;
    float4 v = hw4[(size_t)node * 64 + t];
    acc.x += v.x * cs; acc.y += v.y * cs; acc.z += v.z * cs; acc.w += v.w * cs;
    float4 bb = ((const float4*)bgcn)[t];
    acc.x = fmaxf(acc.x + bb.x, 0.f);
    acc.y = fmaxf(acc.y + bb.y, 0.f);
    acc.z = fmaxf(acc.z + bb.z, 0.f);
    acc.w = fmaxf(acc.w + bb.w, 0.f);
    ((float4*)g_h)[(size_t)node * 64 + t] = acc;
}

// ---------------- proto = mean_n t, pn = ||proto|| ----------------
__global__ void proto_kernel() {
    int b = blockIdx.x;
    int h = threadIdx.x;   // 256
    const float* tb = g_t + (size_t)b * NN * HH;
    float s = 0.f;
    for (int n = 0; n < NN; n++) s += tb[(size_t)n * HH + h];
    s *= (1.0f / NN);
    g_proto[b * HH + h] = s;
    __shared__ float red[256];
    red[h] = s * s;
    __syncthreads();
    for (int off = 128; off > 0; off >>= 1) {
        if (h < off) red[h] += red[h + off];
        __syncthreads();
    }
    if (h == 0) g_pn[b] = fmaxf(sqrtf(red[0]), 1e-8f);
}

// ---------------- fused attention + mw (warp per node) ----------------
__global__ void att_mw_kernel(const float* __restrict__ ew) {
    int w = (blockIdx.x * blockDim.x + threadIdx.x) >> 5;
    int lane = threadIdx.x & 31;
    if (w >= TOTAL_NODES) return;
    int b = w >> 9;
    const float* tr = g_t + (size_t)w * HH;
    const float* pr = g_proto + b * HH;
    float dot = 0.f, nrm = 0.f;
    for (int j = lane; j < HH; j += 32) {
        float v = tr[j];
        dot += v * pr[j];
        nrm += v * v;
    }
#pragma unroll
    for (int off = 16; off; off >>= 1) {
        dot += __shfl_xor_sync(0xffffffffu, dot, off);
        nrm += __shfl_xor_sync(0xffffffffu, nrm, off);
    }
    float tn = fmaxf(sqrtf(nrm), 1e-8f);
    float sim = dot / (tn * g_pn[b]);
    float a = 0.5f * (1.0f + sim);

    const float* e = ew + (size_t)w * VV;
    float v0 = e[lane] * a;
    float v1 = e[lane + 32] * a;
    float rs = v0 + v1;
#pragma unroll
    for (int off = 16; off; off >>= 1) rs += __shfl_xor_sync(0xffffffffu, rs, off);
    float sc = (rs == 0.0f) ? 1.0f : (1.0f / rs);
    float* m = g_mw + (size_t)w * VV;
    m[lane]      = v0 * sc;
    m[lane + 32] = v1 * sc;
}

// ---------------- gf = mean over V ----------------
__global__ void gf_kernel() {
    int b = blockIdx.x, h = threadIdx.x;
    const float* v = g_vn3 + (size_t)b * VV * HH;
    float s = 0.f;
    for (int i = 0; i < VV; i++) s += v[i * HH + h];
    g_gf[b * HH + h] = s * (1.0f / VV);
}

// ---------------- out = m1 @ mW2 + mb2 ----------------
__global__ void out_kernel(const float* __restrict__ W, const float* __restrict__ bias,
                           float* __restrict__ out)
{
    int tid = threadIdx.x;
    if (tid >= BG * OUTD) return;
    int b = tid / OUTD, o = tid % OUTD;
    const float* m = g_m1 + b * HH;
    float s = bias[o];
    for (int k = 0; k < HH; k++) s += m[k] * W[k * OUTD + o];
    out[tid] = s;
}

// ---------------- launch ----------------
extern "C" void kernel_launch(void* const* d_in, const int* in_sizes, int n_in,
                              void* d_out, int out_size)
{
    const float* x     = (const float*)d_in[0];
    const int*   esrc  = (const int*)  d_in[1];
    const int*   edst  = (const int*)  d_in[2];
    const float* W_emb = (const float*)d_in[3];
    const float* b_emb = (const float*)d_in[4];
    const float* W_gcn = (const float*)d_in[5];
    const float* b_gcn = (const float*)d_in[6];
    const float* aW1   = (const float*)d_in[7];
    const float* ab1   = (const float*)d_in[8];
    const float* aW2   = (const float*)d_in[9];
    const float* ab2   = (const float*)d_in[10];
    const float* vW1   = (const float*)d_in[11];
    const float* vb1   = (const float*)d_in[12];
    const float* vW2   = (const float*)d_in[13];
    const float* vb2   = (const float*)d_in[14];
    const float* mW1   = (const float*)d_in[15];
    const float* mb1   = (const float*)d_in[16];
    const float* mW2   = (const float*)d_in[17];
    const float* mb2   = (const float*)d_in[18];
    const float* ew    = (const float*)d_in[19];
    float* out = (float*)d_out;

    float *h, *hw, *t1, *t, *mw, *vn, *vn2, *vn3, *gf, *m1;
    __nv_bfloat16 *wh, *wl;
    cudaGetSymbolAddress((void**)&h,   g_h);
    cudaGetSymbolAddress((void**)&hw,  g_hw);
    cudaGetSymbolAddress((void**)&t1,  g_t1);
    cudaGetSymbolAddress((void**)&t,   g_t);
    cudaGetSymbolAddress((void**)&mw,  g_mw);
    cudaGetSymbolAddress((void**)&vn,  g_vn);
    cudaGetSymbolAddress((void**)&vn2, g_vn2);
    cudaGetSymbolAddress((void**)&vn3, g_vn3);
    cudaGetSymbolAddress((void**)&gf,  g_gf);
    cudaGetSymbolAddress((void**)&m1,  g_m1);
    cudaGetSymbolAddress((void**)&wh,  g_wh);
    cudaGetSymbolAddress((void**)&wl,  g_wl);

    static bool attr_done = false;
    if (!attr_done) {
        cudaFuncSetAttribute(gemm_mma_kernel<false, true>,  cudaFuncAttributeMaxDynamicSharedMemorySize, GEMM_SMEM);
        cudaFuncSetAttribute(gemm_mma_kernel<false, false>, cudaFuncAttributeMaxDynamicSharedMemorySize, GEMM_SMEM);
        cudaFuncSetAttribute(gemm_mma_kernel<true,  true>,  cudaFuncAttributeMaxDynamicSharedMemorySize, GEMM_SMEM);
        attr_done = true;
    }

    dim3 t2d(16, 16);
    const int WS = 256 * 256;   // weight slot stride

    // launches 1-3
    split_all_kernel<<<dim3(256, 6), 256>>>(W_emb, W_gcn, aW1, aW2, vW1, vW2);
    zero_cursor_kernel<<<TOTAL_NODES / 256, 256>>>();
    fill_kernel<<<EE / 256, 256>>>(esrc, edst);

    // launch 4: first big GEMM (profiler lands here)
    gemm_mma_kernel<false, true><<<dim3(HH / 128, TOTAL_NODES / 64), 256, GEMM_SMEM>>>(
        x, wh + 0 * WS, wl + 0 * WS, b_emb, h, TOTAL_NODES, HH, INF_);

    dinv_kernel<<<TOTAL_NODES / 256, 256>>>();

    // hw = h @ W_gcn
    gemm_mma_kernel<false, false><<<dim3(HH / 128, TOTAL_NODES / 64), 256, GEMM_SMEM>>>(
        h, wh + 1 * WS, wl + 1 * WS, nullptr, hw, TOTAL_NODES, HH, HH);
    // g = relu(agg + b_gcn)  (overwrites g_h)
    gather_gcn_kernel<<<TOTAL_NODES / 4, dim3(64, 4)>>>(b_gcn);

    // t = relu(g@aW1+ab1)@aW2+ab2
    gemm_mma_kernel<true, true><<<dim3(HH / 128, TOTAL_NODES / 64), 256, GEMM_SMEM>>>(
        h, wh + 2 * WS, wl + 2 * WS, ab1, t1, TOTAL_NODES, HH, HH);
    gemm_mma_kernel<false, true><<<dim3(HH / 128, TOTAL_NODES / 64), 256, GEMM_SMEM>>>(
        t1, wh + 3 * WS, wl + 3 * WS, ab2, t, TOTAL_NODES, HH, HH);

    // attention
    proto_kernel<<<BG, 256>>>();
    att_mw_kernel<<<TOTAL_NODES * 32 / 256, 256>>>(ew);

    // vn = mw^T @ g (per graph) via mma, then vn MLP
    vn_mma_kernel<<<dim3(2, BG), 256>>>(mw, h, vn);
    gemm_mma_kernel<true, true><<<dim3(HH / 128, BG * VV / 64), 256, GEMM_SMEM>>>(
        vn, wh + 4 * WS, wl + 4 * WS, vb1, vn2, BG * VV, HH, HH);
    gemm_mma_kernel<false, true><<<dim3(HH / 128, BG * VV / 64), 256, GEMM_SMEM>>>(
        vn2, wh + 5 * WS, wl + 5 * WS, vb2, vn3, BG * VV, HH, HH);

    // readout
    gf_kernel<<<BG, 256>>>();
    gemm_kernel<true, true><<<dim3(HH / 64, 1), t2d>>>(gf, mW1, mb1, m1, BG, HH, HH);
    out_kernel<<<1, 640>>>(mW2, mb2, out);
}

// round 14
// speedup vs baseline: 1.6090x; 1.1657x over previous
#include <cuda_runtime.h>
#include <cuda_bf16.h>
#include <math.h>
#include <cstdint>

// Problem constants (fixed shapes from the reference)
#define TOTAL_NODES 32768
#define BG   64
#define NN   512
#define VV   64
#define EE   1048576
#define INF_ 128
#define HH   256
#define OUTD 10
#define BUCKET 128   // fixed CSR bucket per node (avg deg 32, P(>128) ~ 0)

// ---------------- scratch (static device globals; no allocation) ----------------
__device__ float g_h  [TOTAL_NODES * HH];   // g (post-GCN)
__device__ float g_hw [TOTAL_NODES * HH];   // holds dinv-prescaled hw
__device__ float g_t1 [TOTAL_NODES * HH];
__device__ float g_t  [TOTAL_NODES * HH];
__device__ float g_proto[BG * HH];
__device__ float g_pn [BG];
__device__ float g_mw [BG * NN * VV];
__device__ float g_vn [BG * VV * HH];
__device__ float g_vn2[BG * VV * HH];
__device__ float g_vn3[BG * VV * HH];
__device__ int   g_cursor[TOTAL_NODES];
__device__ float g_dinv  [TOTAL_NODES];
__device__ int   g_csr   [TOTAL_NODES * BUCKET];   // 16 MB fixed-stride buckets
// pre-split transposed weights: 6 slots of [N,K] bf16 (slot stride 256*256)
__device__ __nv_bfloat16 g_wh[6 * 256 * 256];
__device__ __nv_bfloat16 g_wl[6 * 256 * 256];

// ---------------- bucket CSR build (no scan) ----------------
__global__ void zero_cursor_kernel() {
    int i = blockIdx.x * blockDim.x + threadIdx.x;
    if (i < TOTAL_NODES) g_cursor[i] = 0;
}

__global__ void fill_kernel(const int* __restrict__ src, const int* __restrict__ dst) {
    int e = blockIdx.x * blockDim.x + threadIdx.x;
    if (e < EE) {
        int d = dst[e];
        int p = atomicAdd(&g_cursor[d], 1);
        g_csr[d * BUCKET + p] = src[e];
    }
}

__global__ void dinv_kernel() {
    int i = blockIdx.x * blockDim.x + threadIdx.x;
    if (i < TOTAL_NODES) g_dinv[i] = rsqrtf(1.0f + (float)g_cursor[i]);
}

// ---------------- fused weight split+transpose: all 6 weights in one launch ----------------
__global__ void split_all_kernel(const float* __restrict__ w0, const float* __restrict__ w1,
                                 const float* __restrict__ w2, const float* __restrict__ w3,
                                 const float* __restrict__ w4, const float* __restrict__ w5) {
    int slot = blockIdx.y;
    const float* W;
    switch (slot) {
        case 0: W = w0; break; case 1: W = w1; break; case 2: W = w2; break;
        case 3: W = w3; break; case 4: W = w4; break; default: W = w5; break;
    }
    int K = (slot == 0) ? INF_ : HH;
    int idx = blockIdx.x * 256 + threadIdx.x;
    if (idx >= K * HH) return;
    int k = idx / HH, n = idx % HH;
    float v = W[idx];
    __nv_bfloat16 hb = __float2bfloat16_rn(v);
    float r = v - __bfloat162float(hb);
    size_t o = (size_t)slot * (256 * 256) + (size_t)n * K + k;
    g_wh[o] = hb;
    g_wl[o] = __float2bfloat16_rn(r);
}

// ---------------- mma.sync bf16-split GEMM ----------------
// 64(M) x 128(N) CTA tile, BK=32, 8 warps (2x4), warp tile 32x32.
// Double-buffered, cp.async for B, ldmatrix fragments, 3 CTAs/SM.
// SCALE: multiply output row r by g_dinv[r] (for GCN prescale).
#define MMA_BF16(d, a, b) \
    asm volatile("mma.sync.aligned.m16n8k16.row.col.f32.bf16.bf16.f32 " \
        "{%0,%1,%2,%3}, {%4,%5,%6,%7}, {%8,%9}, {%0,%1,%2,%3};" \
        : "+f"((d)[0]), "+f"((d)[1]), "+f"((d)[2]), "+f"((d)[3]) \
        : "r"((a)[0]), "r"((a)[1]), "r"((a)[2]), "r"((a)[3]), "r"((b)[0]), "r"((b)[1]))

#define LDSM4(r0, r1, r2, r3, addr) \
    asm volatile("ldmatrix.sync.aligned.m8n8.x4.shared.b16 {%0,%1,%2,%3}, [%4];" \
        : "=r"(r0), "=r"(r1), "=r"(r2), "=r"(r3) : "r"(addr))

#define APITCH 80                     // bytes per 32-bf16 row (64B data + 16B pad)
#define A_TILE (64 * APITCH)          // 5120
#define B_TILE (128 * APITCH)         // 10240
#define BUF_BYTES (2 * A_TILE + 2 * B_TILE)   // 30720: Ah, Al, Bh, Bl
#define OFF_AL  A_TILE
#define OFF_BH  (2 * A_TILE)
#define OFF_BL  (2 * A_TILE + B_TILE)
#define GEMM_SMEM (2 * BUF_BYTES)     // 61440

__device__ __forceinline__ uint32_t smem_u32(const void* p) {
    uint32_t a;
    asm("{ .reg .u64 t; cvta.to.shared.u64 t, %1; cvt.u32.u64 %0, t; }" : "=r"(a) : "l"(p));
    return a;
}
#define CP_ASYNC16(saddr, gptr) \
    asm volatile("cp.async.cg.shared.global [%0], [%1], 16;" :: "r"(saddr), "l"(gptr))
#define CP_COMMIT() asm volatile("cp.async.commit_group;" ::: "memory")
#define CP_WAIT0()  asm volatile("cp.async.wait_group 0;" ::: "memory")

__device__ __forceinline__ uint32_t pack_split_hi(float a, float b,
                                                  __nv_bfloat16& ha, __nv_bfloat16& hb) {
    ha = __float2bfloat16_rn(a);
    hb = __float2bfloat16_rn(b);
    return (uint32_t)__bfloat16_as_ushort(ha) | ((uint32_t)__bfloat16_as_ushort(hb) << 16);
}
__device__ __forceinline__ uint32_t pack_lo(float a, float b, __nv_bfloat16 ha, __nv_bfloat16 hb) {
    __nv_bfloat16 la = __float2bfloat16_rn(a - __bfloat162float(ha));
    __nv_bfloat16 lb = __float2bfloat16_rn(b - __bfloat162float(hb));
    return (uint32_t)__bfloat16_as_ushort(la) | ((uint32_t)__bfloat16_as_ushort(lb) << 16);
}

template<bool RELU, bool BIAS, bool SCALE>
__global__ void __launch_bounds__(256, 3) gemm_mma_kernel(
    const float* __restrict__ A,
    const __nv_bfloat16* __restrict__ Bh, const __nv_bfloat16* __restrict__ Bl,
    const float* __restrict__ bias, float* __restrict__ C,
    int M, int N, int K)
{
    extern __shared__ char smem[];
    const uint32_t sb32 = smem_u32(smem);

    const int tid = threadIdx.x;
    const int wid = tid >> 5, lane = tid & 31;
    const int warp_m = wid & 1;       // 2 x 32 rows
    const int warp_n = wid >> 1;      // 4 x 32 cols
    const int row0 = blockIdx.y * 64, col0 = blockIdx.x * 128;

    const int mat = lane >> 3, r8 = lane & 7;
    const uint32_t aoff = (uint32_t)((warp_m * 32 + (mat & 1) * 8 + r8) * APITCH + (mat >> 1) * 16);
    const uint32_t boff = (uint32_t)((warp_n * 32 + (mat >> 1) * 8 + r8) * APITCH + (mat & 1) * 16);

    float acc[2][4][4];
#pragma unroll
    for (int i = 0; i < 2; i++)
#pragma unroll
        for (int j = 0; j < 4; j++)
#pragma unroll
            for (int q = 0; q < 4; q++) acc[i][j][q] = 0.f;

    const int nk = K >> 5;
    float4 pa[2];

    auto ldg_A = [&](int kc) {
#pragma unroll
        for (int it = 0; it < 2; it++) {
            int i = tid + it * 256;
            int r = i >> 3, kq = i & 7;
            pa[it] = *(const float4*)(A + (size_t)(row0 + r) * K + kc + kq * 4);
        }
    };
    auto sts_A = [&](int bb) {
        char* dAh = smem + bb * BUF_BYTES;
        char* dAl = dAh + OFF_AL;
#pragma unroll
        for (int it = 0; it < 2; it++) {
            int i = tid + it * 256;
            int r = i >> 3, kq = i & 7;
            float4 v = pa[it];
            __nv_bfloat16 h0, h1, h2, h3;
            uint2 uh, ul;
            uh.x = pack_split_hi(v.x, v.y, h0, h1);
            uh.y = pack_split_hi(v.z, v.w, h2, h3);
            ul.x = pack_lo(v.x, v.y, h0, h1);
            ul.y = pack_lo(v.z, v.w, h2, h3);
            *(uint2*)(dAh + r * APITCH + kq * 8) = uh;
            *(uint2*)(dAl + r * APITCH + kq * 8) = ul;
        }
    };
    auto cpasync_B = [&](int kc, int bb) {
        uint32_t dBh = sb32 + bb * BUF_BYTES + OFF_BH;
        uint32_t dBl = sb32 + bb * BUF_BYTES + OFF_BL;
#pragma unroll
        for (int it = 0; it < 2; it++) {
            int i = tid + it * 256;
            int n = i >> 2, kq = i & 3;
            size_t goff = (size_t)(col0 + n) * K + kc + kq * 8;
            CP_ASYNC16(dBh + n * APITCH + kq * 16, Bh + goff);
            CP_ASYNC16(dBl + n * APITCH + kq * 16, Bl + goff);
        }
        CP_COMMIT();
    };

    ldg_A(0);
    cpasync_B(0, 0);
    sts_A(0);
    CP_WAIT0();
    __syncthreads();

    int buf = 0;
    for (int c = 0; c < nk; c++) {
        if (c + 1 < nk) {
            ldg_A((c + 1) << 5);
            cpasync_B((c + 1) << 5, buf ^ 1);
        }

        const uint32_t base = sb32 + buf * BUF_BYTES;
#pragma unroll
        for (int ks = 0; ks < 2; ks++) {
            const int kb = ks * 32;
            uint32_t ah[2][4], al[2][4];
            LDSM4(ah[0][0], ah[0][1], ah[0][2], ah[0][3], base + aoff + kb);
            LDSM4(ah[1][0], ah[1][1], ah[1][2], ah[1][3], base + aoff + kb + 16 * APITCH);
            LDSM4(al[0][0], al[0][1], al[0][2], al[0][3], base + OFF_AL + aoff + kb);
            LDSM4(al[1][0], al[1][1], al[1][2], al[1][3], base + OFF_AL + aoff + kb + 16 * APITCH);
#pragma unroll
            for (int p = 0; p < 2; p++) {
                uint32_t bq = base + OFF_BH + boff + kb + p * 16 * APITCH;
                uint32_t bhv[4], blv[4];
                LDSM4(bhv[0], bhv[1], bhv[2], bhv[3], bq);
                LDSM4(blv[0], blv[1], blv[2], blv[3], bq + B_TILE);
#pragma unroll
                for (int sub = 0; sub < 2; sub++) {
                    uint32_t bh2[2] = {bhv[2 * sub], bhv[2 * sub + 1]};
                    uint32_t bl2[2] = {blv[2 * sub], blv[2 * sub + 1]};
                    const int nt = 2 * p + sub;
#pragma unroll
                    for (int mt = 0; mt < 2; mt++) {
                        MMA_BF16(acc[mt][nt], ah[mt], bh2);
                        MMA_BF16(acc[mt][nt], ah[mt], bl2);
                        MMA_BF16(acc[mt][nt], al[mt], bh2);
                    }
                }
            }
        }

        if (c + 1 < nk) {
            sts_A(buf ^ 1);
            CP_WAIT0();
        }
        __syncthreads();
        buf ^= 1;
    }

#pragma unroll
    for (int mt = 0; mt < 2; mt++) {
        int r0 = row0 + warp_m * 32 + mt * 16 + (lane >> 2);
        float s0 = 1.f, s1 = 1.f;
        if (SCALE) { s0 = g_dinv[r0]; s1 = g_dinv[r0 + 8]; }
#pragma unroll
        for (int nt = 0; nt < 4; nt++) {
            int c = col0 + warp_n * 32 + nt * 8 + (lane & 3) * 2;
            float v0 = acc[mt][nt][0], v1 = acc[mt][nt][1];
            float v2 = acc[mt][nt][2], v3 = acc[mt][nt][3];
            if (BIAS) {
                float b0 = bias[c], b1 = bias[c + 1];
                v0 += b0; v1 += b1; v2 += b0; v3 += b1;
            }
            if (SCALE) { v0 *= s0; v1 *= s0; v2 *= s1; v3 *= s1; }
            if (RELU) {
                v0 = fmaxf(v0, 0.f); v1 = fmaxf(v1, 0.f);
                v2 = fmaxf(v2, 0.f); v3 = fmaxf(v3, 0.f);
            }
            *(float2*)(C + (size_t)r0 * N + c) = make_float2(v0, v1);
            *(float2*)(C + (size_t)(r0 + 8) * N + c) = make_float2(v2, v3);
        }
    }
}

// ---------------- vn mma GEMM: vn[b] = mw[b]^T (64x512) @ g[b] (512x256) ----------------
__global__ void __launch_bounds__(256) vn_mma_kernel(
    const float* __restrict__ mw, const float* __restrict__ gfeat, float* __restrict__ vn)
{
    __shared__ __align__(16) char sAh[64 * APITCH];
    __shared__ __align__(16) char sAl[64 * APITCH];
    __shared__ __align__(16) char sBh[128 * APITCH];
    __shared__ __align__(16) char sBl[128 * APITCH];

    const int b = blockIdx.y;
    const int col0 = blockIdx.x * 128;
    const float* mwb = mw + (size_t)b * NN * VV;
    const float* gb  = gfeat + (size_t)b * NN * HH;
    float* vnb = vn + (size_t)b * VV * HH;

    const int tid = threadIdx.x;
    const int wid = tid >> 5, lane = tid & 31;
    const int warp_m = wid & 1;
    const int warp_n = wid >> 1;
    const int lr = lane >> 2;
    const int lk4 = (lane & 3) * 4;

    float acc[2][4][4];
#pragma unroll
    for (int i = 0; i < 2; i++)
#pragma unroll
        for (int j = 0; j < 4; j++)
#pragma unroll
            for (int q = 0; q < 4; q++) acc[i][j][q] = 0.f;

    for (int kc = 0; kc < NN; kc += 32) {
#pragma unroll
        for (int it = 0; it < 4; it++) {
            int i = tid + it * 256;
            int v = i & 63, kp = i >> 6;
            float x0 = mwb[(size_t)(kc + 2 * kp) * VV + v];
            float x1 = mwb[(size_t)(kc + 2 * kp + 1) * VV + v];
            __nv_bfloat16 h0, h1;
            uint32_t uh = pack_split_hi(x0, x1, h0, h1);
            uint32_t ul = pack_lo(x0, x1, h0, h1);
            *(uint32_t*)(sAh + v * APITCH + kp * 4) = uh;
            *(uint32_t*)(sAl + v * APITCH + kp * 4) = ul;
        }
#pragma unroll
        for (int it = 0; it < 8; it++) {
            int i = tid + it * 256;
            int n = i & 127, kp = i >> 7;
            float x0 = gb[(size_t)(kc + 2 * kp) * HH + col0 + n];
            float x1 = gb[(size_t)(kc + 2 * kp + 1) * HH + col0 + n];
            __nv_bfloat16 h0, h1;
            uint32_t uh = pack_split_hi(x0, x1, h0, h1);
            uint32_t ul = pack_lo(x0, x1, h0, h1);
            *(uint32_t*)(sBh + n * APITCH + kp * 4) = uh;
            *(uint32_t*)(sBl + n * APITCH + kp * 4) = ul;
        }
        __syncthreads();

#pragma unroll
        for (int ks = 0; ks < 2; ks++) {
            const int kb = ks * 32;
            uint32_t ah[2][4], al[2][4];
#pragma unroll
            for (int mt = 0; mt < 2; mt++) {
                const char* base = sAh + (warp_m * 32 + mt * 16 + lr) * APITCH + kb + lk4;
                ah[mt][0] = *(const uint32_t*)base;
                ah[mt][1] = *(const uint32_t*)(base + 8 * APITCH);
                ah[mt][2] = *(const uint32_t*)(base + 16);
                ah[mt][3] = *(const uint32_t*)(base + 8 * APITCH + 16);
                const char* basel = sAl + (warp_m * 32 + mt * 16 + lr) * APITCH + kb + lk4;
                al[mt][0] = *(const uint32_t*)basel;
                al[mt][1] = *(const uint32_t*)(basel + 8 * APITCH);
                al[mt][2] = *(const uint32_t*)(basel + 16);
                al[mt][3] = *(const uint32_t*)(basel + 8 * APITCH + 16);
            }
#pragma unroll
            for (int nt = 0; nt < 4; nt++) {
                const char* bbase = sBh + (warp_n * 32 + nt * 8 + lr) * APITCH + kb + lk4;
                uint32_t bh[2], bl[2];
                bh[0] = *(const uint32_t*)bbase;
                bh[1] = *(const uint32_t*)(bbase + 16);
                const char* bbl = sBl + (warp_n * 32 + nt * 8 + lr) * APITCH + kb + lk4;
                bl[0] = *(const uint32_t*)bbl;
                bl[1] = *(const uint32_t*)(bbl + 16);
#pragma unroll
                for (int mt = 0; mt < 2; mt++) {
                    MMA_BF16(acc[mt][nt], ah[mt], bh);
                    MMA_BF16(acc[mt][nt], ah[mt], bl);
                    MMA_BF16(acc[mt][nt], al[mt], bh);
                }
            }
        }
        __syncthreads();
    }

#pragma unroll
    for (int mt = 0; mt < 2; mt++) {
        int r0 = warp_m * 32 + mt * 16 + lr;
#pragma unroll
        for (int nt = 0; nt < 4; nt++) {
            int c = col0 + warp_n * 32 + nt * 8 + (lane & 3) * 2;
            *(float2*)(vnb + (size_t)r0 * HH + c) = make_float2(acc[mt][nt][0], acc[mt][nt][1]);
            *(float2*)(vnb + (size_t)(r0 + 8) * HH + c) = make_float2(acc[mt][nt][2], acc[mt][nt][3]);
        }
    }
}

// ---------------- GCN gather (bucket CSR, prescaled hw, MLP=4) + scale + bias + relu ----------------
__global__ void gather_gcn_kernel(const float* __restrict__ bgcn) {
    int node = blockIdx.x * 4 + threadIdx.y;
    int t = threadIdx.x;              // 0..63
    const float4* hw4 = (const float4*)g_hw;    // prescaled by dinv[row]
    const int* csr = g_csr + node * BUCKET;
    int deg = g_cursor[node];
    float di = g_dinv[node];
    float4 acc = make_float4(0.f, 0.f, 0.f, 0.f);
    int e = 0;
    for (; e + 4 <= deg; e += 4) {
        int s0 = csr[e], s1 = csr[e + 1], s2 = csr[e + 2], s3 = csr[e + 3];
        float4 v0 = hw4[(size_t)s0 * 64 + t];
        float4 v1 = hw4[(size_t)s1 * 64 + t];
        float4 v2 = hw4[(size_t)s2 * 64 + t];
        float4 v3 = hw4[(size_t)s3 * 64 + t];
        acc.x += v0.x + v1.x + v2.x + v3.x;
        acc.y += v0.y + v1.y + v2.y + v3.y;
        acc.z += v0.z + v1.z + v2.z + v3.z;
        acc.w += v0.w + v1.w + v2.w + v3.w;
    }
    for (; e < deg; e++) {
        int s = csr[e];
        float4 v = hw4[(size_t)s * 64 + t];
        acc.x += v.x; acc.y += v.y; acc.z += v.z; acc.w += v.w;
    }
    // self loop: prescaled hw[node] = dinv_d*hw_d; add then scale whole sum by dinv_d
    float4 vs = hw4[(size_t)node * 64 + t];
    acc.x = (acc.x + vs.x) * di;
    acc.y = (acc.y + vs.y) * di;
    acc.z = (acc.z + vs.z) * di;
    acc.w = (acc.w + vs.w) * di;
    float4 bb = ((const float4*)bgcn)[t];
    acc.x = fmaxf(acc.x + bb.x, 0.f);
    acc.y = fmaxf(acc.y + bb.y, 0.f);
    acc.z = fmaxf(acc.z + bb.z, 0.f);
    acc.w = fmaxf(acc.w + bb.w, 0.f);
    ((float4*)g_h)[(size_t)node * 64 + t] = acc;
}

// ---------------- proto = mean_n t, pn = ||proto|| ----------------
__global__ void proto_kernel() {
    int b = blockIdx.x;
    int h = threadIdx.x;   // 256
    const float* tb = g_t + (size_t)b * NN * HH;
    float s = 0.f;
    for (int n = 0; n < NN; n++) s += tb[(size_t)n * HH + h];
    s *= (1.0f / NN);
    g_proto[b * HH + h] = s;
    __shared__ float red[256];
    red[h] = s * s;
    __syncthreads();
    for (int off = 128; off > 0; off >>= 1) {
        if (h < off) red[h] += red[h + off];
        __syncthreads();
    }
    if (h == 0) g_pn[b] = fmaxf(sqrtf(red[0]), 1e-8f);
}

// ---------------- fused attention + mw (warp per node) ----------------
__global__ void att_mw_kernel(const float* __restrict__ ew) {
    int w = (blockIdx.x * blockDim.x + threadIdx.x) >> 5;
    int lane = threadIdx.x & 31;
    if (w >= TOTAL_NODES) return;
    int b = w >> 9;
    const float* tr = g_t + (size_t)w * HH;
    const float* pr = g_proto + b * HH;
    float dot = 0.f, nrm = 0.f;
    for (int j = lane; j < HH; j += 32) {
        float v = tr[j];
        dot += v * pr[j];
        nrm += v * v;
    }
#pragma unroll
    for (int off = 16; off; off >>= 1) {
        dot += __shfl_xor_sync(0xffffffffu, dot, off);
        nrm += __shfl_xor_sync(0xffffffffu, nrm, off);
    }
    float tn = fmaxf(sqrtf(nrm), 1e-8f);
    float sim = dot / (tn * g_pn[b]);
    float a = 0.5f * (1.0f + sim);

    const float* e = ew + (size_t)w * VV;
    float v0 = e[lane] * a;
    float v1 = e[lane + 32] * a;
    float rs = v0 + v1;
#pragma unroll
    for (int off = 16; off; off >>= 1) rs += __shfl_xor_sync(0xffffffffu, rs, off);
    float sc = (rs == 0.0f) ? 1.0f : (1.0f / rs);
    float* m = g_mw + (size_t)w * VV;
    m[lane]      = v0 * sc;
    m[lane + 32] = v1 * sc;
}

// ---------------- fused readout: gf = mean_V vn3; m1 = relu(gf@mW1+mb1); out = m1@mW2+mb2 ----------------
__global__ void __launch_bounds__(256) readout_kernel(
    const float* __restrict__ mW1, const float* __restrict__ mb1,
    const float* __restrict__ mW2, const float* __restrict__ mb2,
    float* __restrict__ out)
{
    __shared__ float sgf[HH];
    __shared__ float sm1[HH];
    const int b = blockIdx.x, h = threadIdx.x;   // 256 threads

    // gf
    const float* v = g_vn3 + (size_t)b * VV * HH;
    float s = 0.f;
#pragma unroll 8
    for (int i = 0; i < VV; i++) s += v[i * HH + h];
    sgf[h] = s * (1.0f / VV);
    __syncthreads();

    // m1[h] = relu(sum_k gf[k]*mW1[k][h] + mb1[h])
    float acc = mb1[h];
    for (int k = 0; k < HH; k++) acc += sgf[k] * mW1[(size_t)k * HH + h];
    sm1[h] = fmaxf(acc, 0.f);
    __syncthreads();

    // out[b][o] = sum_k m1[k]*mW2[k][o] + mb2[o]
    if (h < OUTD) {
        float o = mb2[h];
        for (int k = 0; k < HH; k++) o += sm1[k] * mW2[(size_t)k * OUTD + h];
        out[b * OUTD + h] = o;
    }
}

// ---------------- launch ----------------
extern "C" void kernel_launch(void* const* d_in, const int* in_sizes, int n_in,
                              void* d_out, int out_size)
{
    const float* x     = (const float*)d_in[0];
    const int*   esrc  = (const int*)  d_in[1];
    const int*   edst  = (const int*)  d_in[2];
    const float* W_emb = (const float*)d_in[3];
    const float* b_emb = (const float*)d_in[4];
    const float* W_gcn = (const float*)d_in[5];
    const float* b_gcn = (const float*)d_in[6];
    const float* aW1   = (const float*)d_in[7];
    const float* ab1   = (const float*)d_in[8];
    const float* aW2   = (const float*)d_in[9];
    const float* ab2   = (const float*)d_in[10];
    const float* vW1   = (const float*)d_in[11];
    const float* vb1   = (const float*)d_in[12];
    const float* vW2   = (const float*)d_in[13];
    const float* vb2   = (const float*)d_in[14];
    const float* mW1   = (const float*)d_in[15];
    const float* mb1   = (const float*)d_in[16];
    const float* mW2   = (const float*)d_in[17];
    const float* mb2   = (const float*)d_in[18];
    const float* ew    = (const float*)d_in[19];
    float* out = (float*)d_out;

    float *h, *hw, *t1, *t, *mw, *vn, *vn2, *vn3;
    __nv_bfloat16 *wh, *wl;
    cudaGetSymbolAddress((void**)&h,   g_h);
    cudaGetSymbolAddress((void**)&hw,  g_hw);
    cudaGetSymbolAddress((void**)&t1,  g_t1);
    cudaGetSymbolAddress((void**)&t,   g_t);
    cudaGetSymbolAddress((void**)&mw,  g_mw);
    cudaGetSymbolAddress((void**)&vn,  g_vn);
    cudaGetSymbolAddress((void**)&vn2, g_vn2);
    cudaGetSymbolAddress((void**)&vn3, g_vn3);
    cudaGetSymbolAddress((void**)&wh,  g_wh);
    cudaGetSymbolAddress((void**)&wl,  g_wl);

    static bool attr_done = false;
    if (!attr_done) {
        cudaFuncSetAttribute(gemm_mma_kernel<false, true,  false>, cudaFuncAttributeMaxDynamicSharedMemorySize, GEMM_SMEM);
        cudaFuncSetAttribute(gemm_mma_kernel<false, false, true>,  cudaFuncAttributeMaxDynamicSharedMemorySize, GEMM_SMEM);
        cudaFuncSetAttribute(gemm_mma_kernel<true,  true,  false>, cudaFuncAttributeMaxDynamicSharedMemorySize, GEMM_SMEM);
        attr_done = true;
    }

    const int WS = 256 * 256;   // weight slot stride

    // launches 1-3
    split_all_kernel<<<dim3(256, 6), 256>>>(W_emb, W_gcn, aW1, aW2, vW1, vW2);
    zero_cursor_kernel<<<TOTAL_NODES / 256, 256>>>();
    fill_kernel<<<EE / 256, 256>>>(esrc, edst);

    // launch 4: first big GEMM (profiler lands here)
    gemm_mma_kernel<false, true, false><<<dim3(HH / 128, TOTAL_NODES / 64), 256, GEMM_SMEM>>>(
        x, wh + 0 * WS, wl + 0 * WS, b_emb, h, TOTAL_NODES, HH, INF_);

    dinv_kernel<<<TOTAL_NODES / 256, 256>>>();

    // hw = (h @ W_gcn) * dinv[row]   (prescaled for gather)
    gemm_mma_kernel<false, false, true><<<dim3(HH / 128, TOTAL_NODES / 64), 256, GEMM_SMEM>>>(
        h, wh + 1 * WS, wl + 1 * WS, nullptr, hw, TOTAL_NODES, HH, HH);
    // g = relu(dinv_d * (sum + self) + b_gcn)  (overwrites g_h)
    gather_gcn_kernel<<<TOTAL_NODES / 4, dim3(64, 4)>>>(b_gcn);

    // t = relu(g@aW1+ab1)@aW2+ab2
    gemm_mma_kernel<true, true, false><<<dim3(HH / 128, TOTAL_NODES / 64), 256, GEMM_SMEM>>>(
        h, wh + 2 * WS, wl + 2 * WS, ab1, t1, TOTAL_NODES, HH, HH);
    gemm_mma_kernel<false, true, false><<<dim3(HH / 128, TOTAL_NODES / 64), 256, GEMM_SMEM>>>(
        t1, wh + 3 * WS, wl + 3 * WS, ab2, t, TOTAL_NODES, HH, HH);

    // attention
    proto_kernel<<<BG, 256>>>();
    att_mw_kernel<<<TOTAL_NODES * 32 / 256, 256>>>(ew);

    // vn = mw^T @ g (per graph) via mma, then vn MLP
    vn_mma_kernel<<<dim3(2, BG), 256>>>(mw, h, vn);
    gemm_mma_kernel<true, true, false><<<dim3(HH / 128, BG * VV / 64), 256, GEMM_SMEM>>>(
        vn, wh + 4 * WS, wl + 4 * WS, vb1, vn2, BG * VV, HH, HH);
    gemm_mma_kernel<false, true, false><<<dim3(HH / 128, BG * VV / 64), 256, GEMM_SMEM>>>(
        vn2, wh + 5 * WS, wl + 5 * WS, vb2, vn3, BG * VV, HH, HH);

    // fused readout (gf + m1 GEMM + out)
    readout_kernel<<<BG, 256>>>(mW1, mb1, mW2, mb2, out);
}